// round 2
// baseline (speedup 1.0000x reference)
#include <cuda_runtime.h>
#include <cuda_bf16.h>
#include <math.h>

// Problem constants (fixed instance): N=50000, E=1600000, D=256, H=8, C=32.
#define DD 256
#define HH 8
#define CC 32
#define MAXN 50176

// ---------------- scratch (device globals; no allocation allowed) ----------
__device__ float g_x[MAXN * DD];       // feat @ W_lin   [N, H*C]
__device__ float g_al[MAXN * HH];      // alpha_l        [N, H]
__device__ float g_ar[MAXN * HH];      // alpha_r        [N, H]
__device__ float g_denom[MAXN * HH];   // softmax denom  [N, H]
__device__ float g_agg[MAXN * DD];     // aggregated msg [N, H*C]

// vectorized no-return global atomic add (sm_90+)
__device__ __forceinline__ void red4(float* p, float4 v) {
    asm volatile("red.global.add.v4.f32 [%0], {%1,%2,%3,%4};"
                 :: "l"(p), "f"(v.x), "f"(v.y), "f"(v.z), "f"(v.w)
                 : "memory");
}

// ---------------- K0: dual GEMM  (X = A@Wlin -> g_x,  Res = A@Wres -> d_out)
// BM=128, BN=128, BK=16, 256 threads, 8x8 microtile.
__global__ __launch_bounds__(256, 2) void gemm_dual(
    const float* __restrict__ A, const float* __restrict__ Wlin,
    const float* __restrict__ Wres, float* __restrict__ Res, int M)
{
    __shared__ float As[16][132];
    __shared__ float Bs[16][132];

    int bm  = blockIdx.x * 128;
    int bn4 = blockIdx.y;                      // 0..3  (512 total cols)
    const float* B = (bn4 < 2) ? Wlin : Wres;
    float* Out     = (bn4 < 2) ? g_x  : Res;
    int bcol = (bn4 & 1) * 128;

    int tid = threadIdx.x;
    int tx = tid & 15, ty = tid >> 4;

    float acc[8][8];
    #pragma unroll
    for (int i = 0; i < 8; i++)
        #pragma unroll
        for (int j = 0; j < 8; j++) acc[i][j] = 0.f;

    for (int kt = 0; kt < DD; kt += 16) {
        // load A tile 128x16 (transpose into As[k][m])
        #pragma unroll
        for (int i = 0; i < 2; i++) {
            int f = tid + i * 256;
            int r = f >> 2, cv = f & 3;
            int grow = bm + r;
            float4 v = make_float4(0.f, 0.f, 0.f, 0.f);
            if (grow < M)
                v = *(const float4*)(A + (size_t)grow * DD + kt + cv * 4);
            As[cv * 4 + 0][r] = v.x;
            As[cv * 4 + 1][r] = v.y;
            As[cv * 4 + 2][r] = v.z;
            As[cv * 4 + 3][r] = v.w;
        }
        // load B tile 16x128
        #pragma unroll
        for (int i = 0; i < 2; i++) {
            int f = tid + i * 256;
            int r = f >> 5, cv = f & 31;
            float4 v = *(const float4*)(B + (size_t)(kt + r) * DD + bcol + cv * 4);
            *(float4*)&Bs[r][cv * 4] = v;
        }
        __syncthreads();
        #pragma unroll
        for (int k = 0; k < 16; k++) {
            float a[8], b[8];
            *(float4*)&a[0] = *(float4*)&As[k][ty * 8];
            *(float4*)&a[4] = *(float4*)&As[k][ty * 8 + 4];
            *(float4*)&b[0] = *(float4*)&Bs[k][tx * 8];
            *(float4*)&b[4] = *(float4*)&Bs[k][tx * 8 + 4];
            #pragma unroll
            for (int i = 0; i < 8; i++)
                #pragma unroll
                for (int j = 0; j < 8; j++)
                    acc[i][j] = fmaf(a[i], b[j], acc[i][j]);
        }
        __syncthreads();
    }
    #pragma unroll
    for (int i = 0; i < 8; i++) {
        int grow = bm + ty * 8 + i;
        if (grow < M) {
            float* o = Out + (size_t)grow * DD + bcol + tx * 8;
            *(float4*)o       = make_float4(acc[i][0], acc[i][1], acc[i][2], acc[i][3]);
            *(float4*)(o + 4) = make_float4(acc[i][4], acc[i][5], acc[i][6], acc[i][7]);
        }
    }
}

// ---------------- K1: per-(node,head) alpha_l/alpha_r + zero denom/agg -----
__global__ void alpha_zero(const float* __restrict__ attl,
                           const float* __restrict__ attr, int N)
{
    __shared__ float sl[DD], sr[DD];
    if (threadIdx.x < DD) {
        sl[threadIdx.x] = attl[threadIdx.x];
        sr[threadIdx.x] = attr[threadIdx.x];
    }
    __syncthreads();
    int idx = blockIdx.x * blockDim.x + threadIdx.x;
    if (idx >= N * HH) return;
    int n = idx >> 3, h = idx & 7;
    const float* xr = g_x + (size_t)n * DD + h * CC;
    const float* al = sl + h * CC;
    const float* ar = sr + h * CC;
    float sa = 0.f, sb = 0.f;
    #pragma unroll
    for (int i = 0; i < CC; i++) {
        float xv = xr[i];
        sa = fmaf(xv, al[i], sa);
        sb = fmaf(xv, ar[i], sb);
    }
    g_al[idx] = sa;
    g_ar[idx] = sb;
    g_denom[idx] = 0.f;
    float4 z = make_float4(0.f, 0.f, 0.f, 0.f);
    float4* ag = (float4*)(g_agg + (size_t)n * DD + h * CC);
    #pragma unroll
    for (int i = 0; i < 8; i++) ag[i] = z;
}

// ---------------- K2: per-edge exp(alpha) accumulated into denom -----------
// No segment-max pass: alpha is bounded (|alpha| <~ 20), exp(alpha)/sum
// is mathematically identical to the max-shifted form in the reference.
__global__ void edge_denom(const int* __restrict__ ei,
                           const float* __restrict__ ew, int E)
{
    int e = blockIdx.x * blockDim.x + threadIdx.x;
    if (e >= E) return;
    int src = ei[e];
    int dst = ei[E + e];
    float w = ew[e];
    float4 al0 = *(const float4*)(g_al + src * HH);
    float4 al1 = *(const float4*)(g_al + src * HH + 4);
    float4 ar0 = *(const float4*)(g_ar + dst * HH);
    float4 ar1 = *(const float4*)(g_ar + dst * HH + 4);
    float a[8];
    a[0] = w * (al0.x + ar0.x); a[1] = w * (al0.y + ar0.y);
    a[2] = w * (al0.z + ar0.z); a[3] = w * (al0.w + ar0.w);
    a[4] = w * (al1.x + ar1.x); a[5] = w * (al1.y + ar1.y);
    a[6] = w * (al1.z + ar1.z); a[7] = w * (al1.w + ar1.w);
    float ex[8];
    #pragma unroll
    for (int h = 0; h < 8; h++) {
        float v = fmaxf(a[h], 0.2f * a[h]);   // leaky_relu(0.2)
        ex[h] = __expf(v);
    }
    red4(g_denom + dst * HH,     make_float4(ex[0], ex[1], ex[2], ex[3]));
    red4(g_denom + dst * HH + 4, make_float4(ex[4], ex[5], ex[6], ex[7]));
}

// ---------------- K3: per-edge weighted message scatter (warp per edge) ----
__global__ void edge_scatter(const int* __restrict__ ei,
                             const float* __restrict__ ew, int E)
{
    int gw = (blockIdx.x * blockDim.x + threadIdx.x) >> 5;
    int lane = threadIdx.x & 31;
    if (gw >= E) return;
    int src = ei[gw];
    int dst = ei[E + gw];
    float w = ew[gw];

    // lanes 0..7 each own one head (others compute redundantly, harmless)
    int h = lane & 7;
    float a = w * (g_al[src * HH + h] + g_ar[dst * HH + h]);
    a = fmaxf(a, 0.2f * a);
    float ex = __expf(a);                       // identical math to K2
    float c  = ex / (g_denom[dst * HH + h] + 1e-16f);
    // element block of this lane: [lane*8, lane*8+8) -> head = lane>>2
    float coeff = __shfl_sync(0xffffffffu, c, lane >> 2);

    const float4* xr = (const float4*)(g_x + (size_t)src * DD + lane * 8);
    float4 v0 = xr[0], v1 = xr[1];
    v0.x *= coeff; v0.y *= coeff; v0.z *= coeff; v0.w *= coeff;
    v1.x *= coeff; v1.y *= coeff; v1.z *= coeff; v1.w *= coeff;
    float* ag = g_agg + (size_t)dst * DD + lane * 8;
    red4(ag, v0);
    red4(ag + 4, v1);
}

// ---------------- K4: out = elu(agg) + res  (res already in d_out) ---------
__global__ void finalize(float* __restrict__ out, int total4)
{
    int i = blockIdx.x * blockDim.x + threadIdx.x;
    if (i >= total4) return;
    float4 a = ((const float4*)g_agg)[i];
    float4 r = ((float4*)out)[i];
    a.x = (a.x > 0.f ? a.x : expm1f(a.x)) + r.x;
    a.y = (a.y > 0.f ? a.y : expm1f(a.y)) + r.y;
    a.z = (a.z > 0.f ? a.z : expm1f(a.z)) + r.z;
    a.w = (a.w > 0.f ? a.w : expm1f(a.w)) + r.w;
    ((float4*)out)[i] = a;
}

// ---------------------------------------------------------------------------
extern "C" void kernel_launch(void* const* d_in, const int* in_sizes, int n_in,
                              void* d_out, int out_size)
{
    const float* feat = (const float*)d_in[0];
    const float* ew   = (const float*)d_in[1];
    const float* Wlin = (const float*)d_in[2];
    const float* attl = (const float*)d_in[3];
    const float* attr = (const float*)d_in[4];
    const float* Wres = (const float*)d_in[5];
    const int*   ei   = (const int*)d_in[6];
    float* out = (float*)d_out;

    int HC = in_sizes[3];            // 256
    int D  = in_sizes[2] / HC;       // 256
    int N  = in_sizes[0] / D;        // 50000
    int E  = in_sizes[1];            // 1600000

    dim3 gGemm((N + 127) / 128, 4);
    gemm_dual<<<gGemm, 256>>>(feat, Wlin, Wres, out, N);

    alpha_zero<<<(N * HH + 255) / 256, 256>>>(attl, attr, N);

    edge_denom<<<(E + 255) / 256, 256>>>(ei, ew, E);

    edge_scatter<<<(E + 7) / 8, 256>>>(ei, ew, E);

    int total4 = N * (DD / 4);
    finalize<<<(total4 + 255) / 256, 256>>>(out, total4);
}

// round 3
// speedup vs baseline: 1.4428x; 1.4428x over previous
#include <cuda_runtime.h>
#include <cuda_bf16.h>
#include <math.h>

// Problem constants (fixed instance): N=50000, E=1600000, D=256, H=8, C=32.
#define DD 256
#define HH 8
#define CC 32
#define MAXN 50176
#define MAXE 1600000

// ---------------- scratch (device globals; no allocation allowed) ----------
__device__ float g_x[MAXN * DD];          // feat @ W_lin   [N, H*C]
__device__ float g_al[MAXN * HH];         // alpha_l        [N, H]
__device__ float g_ar[MAXN * HH];         // alpha_r        [N, H]
__device__ int   g_cnt[MAXN + 1];         // per-dst degree histogram
__device__ int   g_off[MAXN + 1];         // exclusive prefix (segment starts)
__device__ int   g_cur[MAXN];             // scatter cursors (mutable copy)
__device__ int   g_ssrc[MAXE];            // dst-sorted: src node per edge
__device__ float g_sw[MAXE];              // dst-sorted: edge weight

// ---------------- K0: dual GEMM  (X = A@Wlin -> g_x,  Res = A@Wres -> d_out)
__global__ __launch_bounds__(256, 2) void gemm_dual(
    const float* __restrict__ A, const float* __restrict__ Wlin,
    const float* __restrict__ Wres, float* __restrict__ Res, int M)
{
    __shared__ float As[16][132];
    __shared__ float Bs[16][132];

    int bm  = blockIdx.x * 128;
    int bn4 = blockIdx.y;                      // 0..3  (512 total cols)
    const float* B = (bn4 < 2) ? Wlin : Wres;
    float* Out     = (bn4 < 2) ? g_x  : Res;
    int bcol = (bn4 & 1) * 128;

    int tid = threadIdx.x;
    int tx = tid & 15, ty = tid >> 4;

    float acc[8][8];
    #pragma unroll
    for (int i = 0; i < 8; i++)
        #pragma unroll
        for (int j = 0; j < 8; j++) acc[i][j] = 0.f;

    for (int kt = 0; kt < DD; kt += 16) {
        #pragma unroll
        for (int i = 0; i < 2; i++) {
            int f = tid + i * 256;
            int r = f >> 2, cv = f & 3;
            int grow = bm + r;
            float4 v = make_float4(0.f, 0.f, 0.f, 0.f);
            if (grow < M)
                v = *(const float4*)(A + (size_t)grow * DD + kt + cv * 4);
            As[cv * 4 + 0][r] = v.x;
            As[cv * 4 + 1][r] = v.y;
            As[cv * 4 + 2][r] = v.z;
            As[cv * 4 + 3][r] = v.w;
        }
        #pragma unroll
        for (int i = 0; i < 2; i++) {
            int f = tid + i * 256;
            int r = f >> 5, cv = f & 31;
            float4 v = *(const float4*)(B + (size_t)(kt + r) * DD + bcol + cv * 4);
            *(float4*)&Bs[r][cv * 4] = v;
        }
        __syncthreads();
        #pragma unroll
        for (int k = 0; k < 16; k++) {
            float a[8], b[8];
            *(float4*)&a[0] = *(float4*)&As[k][ty * 8];
            *(float4*)&a[4] = *(float4*)&As[k][ty * 8 + 4];
            *(float4*)&b[0] = *(float4*)&Bs[k][tx * 8];
            *(float4*)&b[4] = *(float4*)&Bs[k][tx * 8 + 4];
            #pragma unroll
            for (int i = 0; i < 8; i++)
                #pragma unroll
                for (int j = 0; j < 8; j++)
                    acc[i][j] = fmaf(a[i], b[j], acc[i][j]);
        }
        __syncthreads();
    }
    #pragma unroll
    for (int i = 0; i < 8; i++) {
        int grow = bm + ty * 8 + i;
        if (grow < M) {
            float* o = Out + (size_t)grow * DD + bcol + tx * 8;
            *(float4*)o       = make_float4(acc[i][0], acc[i][1], acc[i][2], acc[i][3]);
            *(float4*)(o + 4) = make_float4(acc[i][4], acc[i][5], acc[i][6], acc[i][7]);
        }
    }
}

// ---------------- K1: per-(node,head) alpha_l/alpha_r + zero histogram -----
__global__ void alpha_hist0(const float* __restrict__ attl,
                            const float* __restrict__ attr, int N)
{
    __shared__ float sl[DD], sr[DD];
    if (threadIdx.x < DD) {
        sl[threadIdx.x] = attl[threadIdx.x];
        sr[threadIdx.x] = attr[threadIdx.x];
    }
    __syncthreads();
    int idx = blockIdx.x * blockDim.x + threadIdx.x;
    if (idx <= N) g_cnt[idx] = 0;
    if (idx >= N * HH) return;
    int n = idx >> 3, h = idx & 7;
    const float* xr = g_x + (size_t)n * DD + h * CC;
    const float* al = sl + h * CC;
    const float* ar = sr + h * CC;
    float sa = 0.f, sb = 0.f;
    #pragma unroll
    for (int i = 0; i < CC; i++) {
        float xv = xr[i];
        sa = fmaf(xv, al[i], sa);
        sb = fmaf(xv, ar[i], sb);
    }
    g_al[idx] = sa;
    g_ar[idx] = sb;
}

// ---------------- K2: histogram of destination degrees ---------------------
__global__ void hist_dst(const int* __restrict__ ei, int E)
{
    int e = blockIdx.x * blockDim.x + threadIdx.x;
    if (e >= E) return;
    atomicAdd(&g_cnt[ei[E + e]], 1);
}

// ---------------- K3: exclusive scan (single block, 1024 threads) ----------
__global__ void scan_off(int N, int E)
{
    __shared__ int s[1024];
    int t = threadIdx.x;
    int chunk = (N + 1023) / 1024;
    int beg = t * chunk;
    int end = min(beg + chunk, N);
    int sum = 0;
    for (int i = beg; i < end; i++) sum += g_cnt[i];
    s[t] = sum;
    __syncthreads();
    // Hillis-Steele inclusive scan
    for (int off = 1; off < 1024; off <<= 1) {
        int v = (t >= off) ? s[t - off] : 0;
        __syncthreads();
        s[t] += v;
        __syncthreads();
    }
    int excl = (t == 0) ? 0 : s[t - 1];
    for (int i = beg; i < end; i++) {
        g_off[i] = excl;
        g_cur[i] = excl;
        excl += g_cnt[i];
    }
    if (t == 0) g_off[N] = E;
}

// ---------------- K4: payload scatter (counting-sort by dst) ---------------
__global__ void scatter_sort(const int* __restrict__ ei,
                             const float* __restrict__ ew, int E)
{
    int e = blockIdx.x * blockDim.x + threadIdx.x;
    if (e >= E) return;
    int dst = ei[E + e];
    int pos = atomicAdd(&g_cur[dst], 1);
    g_ssrc[pos] = ei[e];
    g_sw[pos]   = ew[e];
}

// ---------------- K5: fused gather + softmax-normalize + elu + residual ----
// One warp per destination node. Accumulates numerator (registers) and
// denominator simultaneously; agg = num/(den+1e-16) is mathematically
// identical to the reference's coeff-per-edge form.
__global__ __launch_bounds__(256) void gather_fused(float* __restrict__ out, int N)
{
    int node = (blockIdx.x * blockDim.x + threadIdx.x) >> 5;
    int lane = threadIdx.x & 31;
    if (node >= N) return;

    int beg = g_off[node];
    int end = g_off[node + 1];
    int hl = lane & 7;
    float ar = g_ar[node * HH + hl];

    float den = 0.f;
    float acc[8];
    #pragma unroll
    for (int k = 0; k < 8; k++) acc[k] = 0.f;

    #pragma unroll 2
    for (int i = beg; i < end; i++) {
        int src = g_ssrc[i];
        float w = g_sw[i];
        float a = w * (g_al[src * HH + hl] + ar);
        a = fmaxf(a, 0.2f * a);                 // leaky_relu(0.2)
        float ex = __expf(a);
        den += ex;                               // valid on lanes 0..7
        float coeff = __shfl_sync(0xffffffffu, ex, lane >> 2);
        const float4* xr = (const float4*)(g_x + (size_t)src * DD + lane * 8);
        float4 v0 = xr[0], v1 = xr[1];
        acc[0] = fmaf(coeff, v0.x, acc[0]);
        acc[1] = fmaf(coeff, v0.y, acc[1]);
        acc[2] = fmaf(coeff, v0.z, acc[2]);
        acc[3] = fmaf(coeff, v0.w, acc[3]);
        acc[4] = fmaf(coeff, v1.x, acc[4]);
        acc[5] = fmaf(coeff, v1.y, acc[5]);
        acc[6] = fmaf(coeff, v1.z, acc[6]);
        acc[7] = fmaf(coeff, v1.w, acc[7]);
    }

    float d = __shfl_sync(0xffffffffu, den, lane >> 2) + 1e-16f;
    float inv = 1.0f / d;

    float* o = out + (size_t)node * DD + lane * 8;   // holds residual
    float4 r0 = *(float4*)o;
    float4 r1 = *(float4*)(o + 4);
    float v;
    v = acc[0] * inv; r0.x += (v > 0.f ? v : expm1f(v));
    v = acc[1] * inv; r0.y += (v > 0.f ? v : expm1f(v));
    v = acc[2] * inv; r0.z += (v > 0.f ? v : expm1f(v));
    v = acc[3] * inv; r0.w += (v > 0.f ? v : expm1f(v));
    v = acc[4] * inv; r1.x += (v > 0.f ? v : expm1f(v));
    v = acc[5] * inv; r1.y += (v > 0.f ? v : expm1f(v));
    v = acc[6] * inv; r1.z += (v > 0.f ? v : expm1f(v));
    v = acc[7] * inv; r1.w += (v > 0.f ? v : expm1f(v));
    *(float4*)o       = r0;
    *(float4*)(o + 4) = r1;
}

// ---------------------------------------------------------------------------
extern "C" void kernel_launch(void* const* d_in, const int* in_sizes, int n_in,
                              void* d_out, int out_size)
{
    const float* feat = (const float*)d_in[0];
    const float* ew   = (const float*)d_in[1];
    const float* Wlin = (const float*)d_in[2];
    const float* attl = (const float*)d_in[3];
    const float* attr = (const float*)d_in[4];
    const float* Wres = (const float*)d_in[5];
    const int*   ei   = (const int*)d_in[6];
    float* out = (float*)d_out;

    int HC = in_sizes[3];            // 256
    int D  = in_sizes[2] / HC;       // 256
    int N  = in_sizes[0] / D;        // 50000
    int E  = in_sizes[1];            // 1600000

    dim3 gGemm((N + 127) / 128, 4);
    gemm_dual<<<gGemm, 256>>>(feat, Wlin, Wres, out, N);

    alpha_hist0<<<(N * HH + 255) / 256, 256>>>(attl, attr, N);

    hist_dst<<<(E + 255) / 256, 256>>>(ei, E);

    scan_off<<<1, 1024>>>(N, E);

    scatter_sort<<<(E + 255) / 256, 256>>>(ei, ew, E);

    gather_fused<<<(N * 32 + 255) / 256, 256>>>(out, N);
}

// round 5
// speedup vs baseline: 1.6258x; 1.1268x over previous
#include <cuda_runtime.h>
#include <cuda_bf16.h>
#include <math.h>

// Problem constants (fixed instance): N=50000, E=1600000, D=256, H=8, C=32.
#define DD 256
#define HH 8
#define CC 32
#define MAXN 50176
#define MAXE 1600000
#define SCAN_BLK 1024          // counts per scan block
#define MAXSB 64               // max scan blocks (49 used)

// ---------------- scratch (device globals; no allocation allowed) ----------
__device__ float g_x[MAXN * DD];          // feat @ W_lin   [N, H*C]
__device__ float g_al[MAXN * HH];         // alpha_l        [N, H]
__device__ float g_ar[MAXN * HH];         // alpha_r        [N, H]
__device__ int   g_cnt[MAXN + 1];         // per-dst degree histogram
__device__ int   g_off[MAXN + 1];         // exclusive prefix (segment starts)
__device__ int   g_cur[MAXN];             // scatter cursors (mutable copy)
__device__ int   g_ssrc[MAXE];            // dst-sorted: src node per edge
__device__ float g_sw[MAXE];              // dst-sorted: edge weight
__device__ int   g_bsum[MAXSB];           // scan: per-block totals
__device__ int   g_bpre[MAXSB];           // scan: per-block exclusive prefix

// ---------------- K0: dual GEMM  (X = A@Wlin -> g_x,  Res = A@Wres -> d_out)
__global__ __launch_bounds__(256, 2) void gemm_dual(
    const float* __restrict__ A, const float* __restrict__ Wlin,
    const float* __restrict__ Wres, float* __restrict__ Res, int M)
{
    __shared__ float As[16][132];
    __shared__ float Bs[16][132];

    int bm  = blockIdx.x * 128;
    int bn4 = blockIdx.y;                      // 0..3  (512 total cols)
    const float* B = (bn4 < 2) ? Wlin : Wres;
    float* Out     = (bn4 < 2) ? g_x  : Res;
    int bcol = (bn4 & 1) * 128;

    int tid = threadIdx.x;
    int tx = tid & 15, ty = tid >> 4;

    float acc[8][8];
    #pragma unroll
    for (int i = 0; i < 8; i++)
        #pragma unroll
        for (int j = 0; j < 8; j++) acc[i][j] = 0.f;

    for (int kt = 0; kt < DD; kt += 16) {
        #pragma unroll
        for (int i = 0; i < 2; i++) {
            int f = tid + i * 256;
            int r = f >> 2, cv = f & 3;
            int grow = bm + r;
            float4 v = make_float4(0.f, 0.f, 0.f, 0.f);
            if (grow < M)
                v = *(const float4*)(A + (size_t)grow * DD + kt + cv * 4);
            As[cv * 4 + 0][r] = v.x;
            As[cv * 4 + 1][r] = v.y;
            As[cv * 4 + 2][r] = v.z;
            As[cv * 4 + 3][r] = v.w;
        }
        #pragma unroll
        for (int i = 0; i < 2; i++) {
            int f = tid + i * 256;
            int r = f >> 5, cv = f & 31;
            float4 v = *(const float4*)(B + (size_t)(kt + r) * DD + bcol + cv * 4);
            *(float4*)&Bs[r][cv * 4] = v;
        }
        __syncthreads();
        #pragma unroll
        for (int k = 0; k < 16; k++) {
            float a[8], b[8];
            *(float4*)&a[0] = *(float4*)&As[k][ty * 8];
            *(float4*)&a[4] = *(float4*)&As[k][ty * 8 + 4];
            *(float4*)&b[0] = *(float4*)&Bs[k][tx * 8];
            *(float4*)&b[4] = *(float4*)&Bs[k][tx * 8 + 4];
            #pragma unroll
            for (int i = 0; i < 8; i++)
                #pragma unroll
                for (int j = 0; j < 8; j++)
                    acc[i][j] = fmaf(a[i], b[j], acc[i][j]);
        }
        __syncthreads();
    }
    #pragma unroll
    for (int i = 0; i < 8; i++) {
        int grow = bm + ty * 8 + i;
        if (grow < M) {
            float* o = Out + (size_t)grow * DD + bcol + tx * 8;
            *(float4*)o       = make_float4(acc[i][0], acc[i][1], acc[i][2], acc[i][3]);
            *(float4*)(o + 4) = make_float4(acc[i][4], acc[i][5], acc[i][6], acc[i][7]);
        }
    }
}

// ---------------- K1: per-(node,head) alpha_l/alpha_r + zero histogram -----
__global__ void alpha_hist0(const float* __restrict__ attl,
                            const float* __restrict__ attr, int N)
{
    __shared__ float sl[DD], sr[DD];
    if (threadIdx.x < DD) {
        sl[threadIdx.x] = attl[threadIdx.x];
        sr[threadIdx.x] = attr[threadIdx.x];
    }
    __syncthreads();
    int idx = blockIdx.x * blockDim.x + threadIdx.x;
    if (idx <= N) g_cnt[idx] = 0;
    if (idx >= N * HH) return;
    int n = idx >> 3, h = idx & 7;
    const float* xr = g_x + (size_t)n * DD + h * CC;
    const float* al = sl + h * CC;
    const float* ar = sr + h * CC;
    float sa = 0.f, sb = 0.f;
    #pragma unroll
    for (int i = 0; i < CC; i++) {
        float xv = xr[i];
        sa = fmaf(xv, al[i], sa);
        sb = fmaf(xv, ar[i], sb);
    }
    g_al[idx] = sa;
    g_ar[idx] = sb;
}

// ---------------- K2: histogram of destination degrees ---------------------
__global__ void hist_dst(const int* __restrict__ ei, int E)
{
    int e = blockIdx.x * blockDim.x + threadIdx.x;
    if (e >= E) return;
    atomicAdd(&g_cnt[ei[E + e]], 1);
}

// ---------------- K3a: per-block totals ------------------------------------
__global__ void scan_phase1(int N)
{
    __shared__ int wsum[8];
    int t = threadIdx.x;
    int base = blockIdx.x * SCAN_BLK + t * 4;
    int s = 0;
    #pragma unroll
    for (int j = 0; j < 4; j++) s += (base + j < N) ? g_cnt[base + j] : 0;
    #pragma unroll
    for (int off = 16; off; off >>= 1) s += __shfl_xor_sync(0xffffffffu, s, off);
    if ((t & 31) == 0) wsum[t >> 5] = s;
    __syncthreads();
    if (t == 0) {
        int tot = 0;
        #pragma unroll
        for (int i = 0; i < 8; i++) tot += wsum[i];
        g_bsum[blockIdx.x] = tot;
    }
}

// ---------------- K3b: scan block totals (1 block, 64 threads) -------------
__global__ void scan_phase2(int nb)
{
    __shared__ int wt[2];
    int t = threadIdx.x;
    int lane = t & 31, wid = t >> 5;
    int mine = (t < nb) ? g_bsum[t] : 0;
    int v = mine;
    #pragma unroll
    for (int off = 1; off < 32; off <<= 1) {
        int u = __shfl_up_sync(0xffffffffu, v, off);
        if (lane >= off) v += u;
    }
    if (lane == 31) wt[wid] = v;
    __syncthreads();
    if (wid == 1) v += wt[0];
    if (t < nb) g_bpre[t] = v - mine;
}

// ---------------- K3c: block-local scan + prefix -> g_off/g_cur ------------
__global__ void scan_phase3(int N, int E)
{
    __shared__ int warp_tot[8];
    int t = threadIdx.x;
    int lane = t & 31, wid = t >> 5;
    int base = blockIdx.x * SCAN_BLK + t * 4;
    int c[4];
    #pragma unroll
    for (int j = 0; j < 4; j++) c[j] = (base + j < N) ? g_cnt[base + j] : 0;
    int tsum = c[0] + c[1] + c[2] + c[3];
    int v = tsum;
    #pragma unroll
    for (int off = 1; off < 32; off <<= 1) {
        int u = __shfl_up_sync(0xffffffffu, v, off);
        if (lane >= off) v += u;
    }
    if (lane == 31) warp_tot[wid] = v;
    __syncthreads();
    if (wid == 0) {
        int wv = (lane < 8) ? warp_tot[lane] : 0;
        #pragma unroll
        for (int off = 1; off < 8; off <<= 1) {
            int u = __shfl_up_sync(0xffffffffu, wv, off);
            if (lane >= off) wv += u;
        }
        if (lane < 8) warp_tot[lane] = wv;
    }
    __syncthreads();
    int excl = v - tsum + ((wid > 0) ? warp_tot[wid - 1] : 0) + g_bpre[blockIdx.x];
    #pragma unroll
    for (int j = 0; j < 4; j++) {
        int idx = base + j;
        if (idx < N) { g_off[idx] = excl; g_cur[idx] = excl; }
        excl += c[j];
    }
    if (blockIdx.x == 0 && t == 0) g_off[N] = E;
}

// ---------------- K4: payload scatter (counting-sort by dst) ---------------
__global__ void scatter_sort(const int* __restrict__ ei,
                             const float* __restrict__ ew, int E)
{
    int e = blockIdx.x * blockDim.x + threadIdx.x;
    if (e >= E) return;
    int dst = ei[E + e];
    int pos = atomicAdd(&g_cur[dst], 1);
    g_ssrc[pos] = ei[e];
    g_sw[pos]   = ew[e];
}

// ---------------- K5: fused gather + softmax-normalize + elu + residual ----
// One warp per destination node; numerator in registers, denominator fused.
__global__ __launch_bounds__(256) void gather_fused(float* __restrict__ out, int N)
{
    int node = (blockIdx.x * blockDim.x + threadIdx.x) >> 5;
    int lane = threadIdx.x & 31;
    if (node >= N) return;

    int beg = g_off[node];
    int end = g_off[node + 1];
    int hl = lane & 7;
    float ar = g_ar[node * HH + hl];

    float den = 0.f;
    float acc[8];
    #pragma unroll
    for (int k = 0; k < 8; k++) acc[k] = 0.f;

    #pragma unroll 2
    for (int i = beg; i < end; i++) {
        int src = g_ssrc[i];
        float w = g_sw[i];
        float a = w * (g_al[src * HH + hl] + ar);
        a = fmaxf(a, 0.2f * a);                 // leaky_relu(0.2)
        float ex = __expf(a);
        den += ex;                               // valid on lanes 0..7
        float coeff = __shfl_sync(0xffffffffu, ex, lane >> 2);
        const float4* xr = (const float4*)(g_x + (size_t)src * DD + lane * 8);
        float4 v0 = xr[0], v1 = xr[1];
        acc[0] = fmaf(coeff, v0.x, acc[0]);
        acc[1] = fmaf(coeff, v0.y, acc[1]);
        acc[2] = fmaf(coeff, v0.z, acc[2]);
        acc[3] = fmaf(coeff, v0.w, acc[3]);
        acc[4] = fmaf(coeff, v1.x, acc[4]);
        acc[5] = fmaf(coeff, v1.y, acc[5]);
        acc[6] = fmaf(coeff, v1.z, acc[6]);
        acc[7] = fmaf(coeff, v1.w, acc[7]);
    }

    float d = __shfl_sync(0xffffffffu, den, lane >> 2) + 1e-16f;
    float inv = 1.0f / d;

    float* o = out + (size_t)node * DD + lane * 8;   // holds residual
    float4 r0 = *(float4*)o;
    float4 r1 = *(float4*)(o + 4);
    float v;
    v = acc[0] * inv; r0.x += (v > 0.f ? v : expm1f(v));
    v = acc[1] * inv; r0.y += (v > 0.f ? v : expm1f(v));
    v = acc[2] * inv; r0.z += (v > 0.f ? v : expm1f(v));
    v = acc[3] * inv; r0.w += (v > 0.f ? v : expm1f(v));
    v = acc[4] * inv; r1.x += (v > 0.f ? v : expm1f(v));
    v = acc[5] * inv; r1.y += (v > 0.f ? v : expm1f(v));
    v = acc[6] * inv; r1.z += (v > 0.f ? v : expm1f(v));
    v = acc[7] * inv; r1.w += (v > 0.f ? v : expm1f(v));
    *(float4*)o       = r0;
    *(float4*)(o + 4) = r1;
}

// ---------------------------------------------------------------------------
extern "C" void kernel_launch(void* const* d_in, const int* in_sizes, int n_in,
                              void* d_out, int out_size)
{
    const float* feat = (const float*)d_in[0];
    const float* ew   = (const float*)d_in[1];
    const float* Wlin = (const float*)d_in[2];
    const float* attl = (const float*)d_in[3];
    const float* attr = (const float*)d_in[4];
    const float* Wres = (const float*)d_in[5];
    const int*   ei   = (const int*)d_in[6];
    float* out = (float*)d_out;

    int HC = in_sizes[3];            // 256
    int D  = in_sizes[2] / HC;       // 256
    int N  = in_sizes[0] / D;        // 50000
    int E  = in_sizes[1];            // 1600000

    dim3 gGemm((N + 127) / 128, 4);
    gemm_dual<<<gGemm, 256>>>(feat, Wlin, Wres, out, N);

    alpha_hist0<<<(N * HH + 255) / 256, 256>>>(attl, attr, N);

    hist_dst<<<(E + 255) / 256, 256>>>(ei, E);

    int nb = (N + SCAN_BLK - 1) / SCAN_BLK;     // 49
    scan_phase1<<<nb, 256>>>(N);
    scan_phase2<<<1, 64>>>(nb);
    scan_phase3<<<nb, 256>>>(N, E);

    scatter_sort<<<(E + 255) / 256, 256>>>(ei, ew, E);

    gather_fused<<<(N * 32 + 255) / 256, 256>>>(out, N);
}

// round 10
// speedup vs baseline: 2.1052x; 1.2949x over previous
#include <cuda_runtime.h>
#include <cuda_bf16.h>
#include <math.h>
#include <stdint.h>

// Problem constants (fixed instance): N=50000, E=1600000, D=256, H=8, C=32.
#define DD 256
#define HH 8
#define CC 32
#define MAXN 50176          // 392 * 128
#define MAXE 1600000
#define SCAN_BLK 1024
#define MAXSB 64
#define NB 512              // total output cols (Wlin | Wres)

// ---------------- scratch (device globals; no allocation allowed) ----------
__device__ float g_x[MAXN * DD];
__device__ float g_al[MAXN * HH];
__device__ float g_ar[MAXN * HH];
__device__ int   g_cnt[MAXN + 1];
__device__ int   g_off[MAXN + 1];
__device__ int   g_cur[MAXN];
__device__ int   g_ssrc[MAXE];
__device__ float g_sw[MAXE];
__device__ int   g_bsum[MAXSB];
__device__ int   g_bpre[MAXSB];
// bf16 hi/lo splits for tensor-core GEMM
__device__ __nv_bfloat16 g_ahi[MAXN * DD];
__device__ __nv_bfloat16 g_alo[MAXN * DD];
__device__ __nv_bfloat16 g_bhi[NB * DD];     // [n][k], k contiguous (W transposed)
__device__ __nv_bfloat16 g_blo[NB * DD];

// ---------------- warp-MMA helpers (baseline PTX, sm_80+) ------------------
__device__ __forceinline__ uint32_t s2u(const void* p) {
    uint32_t a;
    asm("{ .reg .u64 t; cvta.to.shared.u64 t, %1; cvt.u32.u64 %0, t; }"
        : "=r"(a) : "l"(p));
    return a;
}
__device__ __forceinline__ void ldsm4(uint32_t* r, uint32_t addr) {
    asm volatile("ldmatrix.sync.aligned.m8n8.x4.shared.b16 {%0,%1,%2,%3}, [%4];"
                 : "=r"(r[0]), "=r"(r[1]), "=r"(r[2]), "=r"(r[3]) : "r"(addr));
}
__device__ __forceinline__ void mma16816(float* d, const uint32_t* a,
                                         const uint32_t* b) {
    asm volatile(
        "mma.sync.aligned.m16n8k16.row.col.f32.bf16.bf16.f32 "
        "{%0,%1,%2,%3}, {%4,%5,%6,%7}, {%8,%9}, {%0,%1,%2,%3};"
        : "+f"(d[0]), "+f"(d[1]), "+f"(d[2]), "+f"(d[3])
        : "r"(a[0]), "r"(a[1]), "r"(a[2]), "r"(a[3]), "r"(b[0]), "r"(b[1]));
}

// ---------------- K-1a: split feat into bf16 hi/lo -------------------------
__global__ void conv_feat(const float* __restrict__ feat, int N)
{
    int i = blockIdx.x * blockDim.x + threadIdx.x;       // float4 index
    if (i >= N * (DD / 4)) return;
    float4 v = ((const float4*)feat)[i];
    __nv_bfloat16 h0 = __float2bfloat16(v.x);
    __nv_bfloat16 h1 = __float2bfloat16(v.y);
    __nv_bfloat16 h2 = __float2bfloat16(v.z);
    __nv_bfloat16 h3 = __float2bfloat16(v.w);
    __nv_bfloat16 l0 = __float2bfloat16(v.x - __bfloat162float(h0));
    __nv_bfloat16 l1 = __float2bfloat16(v.y - __bfloat162float(h1));
    __nv_bfloat16 l2 = __float2bfloat16(v.z - __bfloat162float(h2));
    __nv_bfloat16 l3 = __float2bfloat16(v.w - __bfloat162float(h3));
    ((__nv_bfloat162*)g_ahi)[i * 2]     = __nv_bfloat162(h0, h1);
    ((__nv_bfloat162*)g_ahi)[i * 2 + 1] = __nv_bfloat162(h2, h3);
    ((__nv_bfloat162*)g_alo)[i * 2]     = __nv_bfloat162(l0, l1);
    ((__nv_bfloat162*)g_alo)[i * 2 + 1] = __nv_bfloat162(l2, l3);
}

// ---------------- K-1b: transpose+split W into B [n][k] bf16 hi/lo ---------
__global__ void conv_w(const float* __restrict__ Wlin, const float* __restrict__ Wres)
{
    int idx = blockIdx.x * blockDim.x + threadIdx.x;     // n*256 + k
    if (idx >= NB * DD) return;
    int n = idx >> 8, k = idx & 255;
    float v = (n < 256) ? Wlin[k * 256 + n] : Wres[k * 256 + (n - 256)];
    __nv_bfloat16 h = __float2bfloat16(v);
    __nv_bfloat16 l = __float2bfloat16(v - __bfloat162float(h));
    g_bhi[idx] = h;
    g_blo[idx] = l;
}

// ---------------- K0: HMMA dual GEMM (mma.sync, 3-term bf16 split) ---------
// CTA: 128x128 output, 256 thr (8 warps, 4m x 2n), BK=32, smem rows 80B pad.
#define LDS 80          // bytes per smem row (40 halves) — conflict-free ldmatrix
__global__ __launch_bounds__(256) void gemm_tc(float* __restrict__ Res, int M)
{
    __shared__ __align__(16) char smAh[128 * LDS];
    __shared__ __align__(16) char smAl[128 * LDS];
    __shared__ __align__(16) char smBh[128 * LDS];
    __shared__ __align__(16) char smBl[128 * LDS];

    int tid = threadIdx.x;
    int wid = tid >> 5, lane = tid & 31;
    int wm = wid >> 1;          // 0..3 -> m offset wm*32
    int wn = wid & 1;           // 0..1 -> n offset wn*64
    int bm = blockIdx.x, bn = blockIdx.y;

    uint32_t aHi = s2u(smAh), aLo = s2u(smAl);
    uint32_t bHi = s2u(smBh), bLo = s2u(smBl);

    // per-lane ldmatrix offsets
    uint32_t offA = (uint32_t)((lane & 15) * LDS + (lane >> 4) * 16);
    uint32_t offB = (uint32_t)(((lane & 7) + ((lane >> 4) & 1) * 8) * LDS +
                               ((lane >> 3) & 1) * 16);

    const __nv_bfloat16* gAh = g_ahi + (size_t)bm * 128 * DD;
    const __nv_bfloat16* gAl = g_alo + (size_t)bm * 128 * DD;
    const __nv_bfloat16* gBh = g_bhi + (size_t)bn * 128 * DD;
    const __nv_bfloat16* gBl = g_blo + (size_t)bn * 128 * DD;

    float acc[2][8][4];
    #pragma unroll
    for (int mt = 0; mt < 2; mt++)
        #pragma unroll
        for (int nt = 0; nt < 8; nt++)
            #pragma unroll
            for (int j = 0; j < 4; j++) acc[mt][nt][j] = 0.f;

    for (int kc = 0; kc < 8; kc++) {            // K chunks of 32
        // global -> smem: 4 tiles of 128 rows x 32 halves (64B), pad to 80B
        const __nv_bfloat16* srcs[4] = {gAh, gAl, gBh, gBl};
        char* dsts[4] = {smAh, smAl, smBh, smBl};
        #pragma unroll
        for (int m = 0; m < 4; m++) {
            const __nv_bfloat16* P = srcs[m] + kc * 32;
            #pragma unroll
            for (int i = 0; i < 2; i++) {
                int t2 = tid * 2 + i;           // 0..511
                int row = t2 >> 2, seg = t2 & 3;
                uint4 v = *(const uint4*)(P + (size_t)row * DD + seg * 8);
                *(uint4*)(dsts[m] + row * LDS + seg * 16) = v;
            }
        }
        __syncthreads();

        #pragma unroll
        for (int ks = 0; ks < 2; ks++) {        // two k=16 steps
            uint32_t kb = ks * 32;
            uint32_t ah[2][4], al[2][4];
            #pragma unroll
            for (int mt = 0; mt < 2; mt++) {
                uint32_t ro = (uint32_t)((wm * 32 + mt * 16) * LDS) + offA + kb;
                ldsm4(ah[mt], aHi + ro);
                ldsm4(al[mt], aLo + ro);
            }
            uint32_t bh[4][4], bl[4][4];
            #pragma unroll
            for (int np = 0; np < 4; np++) {
                uint32_t ro = (uint32_t)((wn * 64 + np * 16) * LDS) + offB + kb;
                ldsm4(bh[np], bHi + ro);
                ldsm4(bl[np], bLo + ro);
            }
            #pragma unroll
            for (int mt = 0; mt < 2; mt++)
                #pragma unroll
                for (int nt = 0; nt < 8; nt++) {
                    float* d = acc[mt][nt];
                    const uint32_t* Bh2 = &bh[nt >> 1][(nt & 1) * 2];
                    const uint32_t* Bl2 = &bl[nt >> 1][(nt & 1) * 2];
                    mma16816(d, ah[mt], Bh2);   // hi*hi
                    mma16816(d, ah[mt], Bl2);   // hi*lo
                    mma16816(d, al[mt], Bh2);   // lo*hi
                }
        }
        __syncthreads();
    }

    // epilogue: write D fragments to g_x (bn 0,1) or Res (bn 2,3)
    #pragma unroll
    for (int mt = 0; mt < 2; mt++) {
        int row0 = bm * 128 + wm * 32 + mt * 16 + (lane >> 2);
        #pragma unroll
        for (int half = 0; half < 2; half++) {
            int row = row0 + half * 8;
            if (row < M) {
                float* base = (bn < 2)
                    ? g_x + (size_t)row * DD + bn * 128
                    : Res + (size_t)row * DD + (bn - 2) * 128;
                #pragma unroll
                for (int nt = 0; nt < 8; nt++) {
                    float2 v = make_float2(acc[mt][nt][half * 2],
                                           acc[mt][nt][half * 2 + 1]);
                    *(float2*)(base + wn * 64 + nt * 8 + (lane & 3) * 2) = v;
                }
            }
        }
    }
}

// ---------------- K1: per-(node,head) alpha_l/alpha_r + zero histogram -----
__global__ void alpha_hist0(const float* __restrict__ attl,
                            const float* __restrict__ attr, int N)
{
    __shared__ float sl[DD], sr[DD];
    if (threadIdx.x < DD) {
        sl[threadIdx.x] = attl[threadIdx.x];
        sr[threadIdx.x] = attr[threadIdx.x];
    }
    __syncthreads();
    int idx = blockIdx.x * blockDim.x + threadIdx.x;
    if (idx <= N) g_cnt[idx] = 0;
    if (idx >= N * HH) return;
    int n = idx >> 3, h = idx & 7;
    const float* xr = g_x + (size_t)n * DD + h * CC;
    const float* al = sl + h * CC;
    const float* ar = sr + h * CC;
    float sa = 0.f, sb = 0.f;
    #pragma unroll
    for (int i = 0; i < CC; i++) {
        float xv = xr[i];
        sa = fmaf(xv, al[i], sa);
        sb = fmaf(xv, ar[i], sb);
    }
    g_al[idx] = sa;
    g_ar[idx] = sb;
}

// ---------------- K2: histogram of destination degrees ---------------------
__global__ void hist_dst(const int* __restrict__ ei, int E)
{
    int e = blockIdx.x * blockDim.x + threadIdx.x;
    if (e >= E) return;
    atomicAdd(&g_cnt[ei[E + e]], 1);
}

// ---------------- K3a/b/c: 3-phase exclusive scan --------------------------
__global__ void scan_phase1(int N)
{
    __shared__ int wsum[8];
    int t = threadIdx.x;
    int base = blockIdx.x * SCAN_BLK + t * 4;
    int s = 0;
    #pragma unroll
    for (int j = 0; j < 4; j++) s += (base + j < N) ? g_cnt[base + j] : 0;
    #pragma unroll
    for (int off = 16; off; off >>= 1) s += __shfl_xor_sync(0xffffffffu, s, off);
    if ((t & 31) == 0) wsum[t >> 5] = s;
    __syncthreads();
    if (t == 0) {
        int tot = 0;
        #pragma unroll
        for (int i = 0; i < 8; i++) tot += wsum[i];
        g_bsum[blockIdx.x] = tot;
    }
}
__global__ void scan_phase2(int nb)
{
    __shared__ int wt[2];
    int t = threadIdx.x;
    int lane = t & 31, wid = t >> 5;
    int mine = (t < nb) ? g_bsum[t] : 0;
    int v = mine;
    #pragma unroll
    for (int off = 1; off < 32; off <<= 1) {
        int u = __shfl_up_sync(0xffffffffu, v, off);
        if (lane >= off) v += u;
    }
    if (lane == 31) wt[wid] = v;
    __syncthreads();
    if (wid == 1) v += wt[0];
    if (t < nb) g_bpre[t] = v - mine;
}
__global__ void scan_phase3(int N, int E)
{
    __shared__ int warp_tot[8];
    int t = threadIdx.x;
    int lane = t & 31, wid = t >> 5;
    int base = blockIdx.x * SCAN_BLK + t * 4;
    int c[4];
    #pragma unroll
    for (int j = 0; j < 4; j++) c[j] = (base + j < N) ? g_cnt[base + j] : 0;
    int tsum = c[0] + c[1] + c[2] + c[3];
    int v = tsum;
    #pragma unroll
    for (int off = 1; off < 32; off <<= 1) {
        int u = __shfl_up_sync(0xffffffffu, v, off);
        if (lane >= off) v += u;
    }
    if (lane == 31) warp_tot[wid] = v;
    __syncthreads();
    if (wid == 0) {
        int wv = (lane < 8) ? warp_tot[lane] : 0;
        #pragma unroll
        for (int off = 1; off < 8; off <<= 1) {
            int u = __shfl_up_sync(0xffffffffu, wv, off);
            if (lane >= off) wv += u;
        }
        if (lane < 8) warp_tot[lane] = wv;
    }
    __syncthreads();
    int excl = v - tsum + ((wid > 0) ? warp_tot[wid - 1] : 0) + g_bpre[blockIdx.x];
    #pragma unroll
    for (int j = 0; j < 4; j++) {
        int idx = base + j;
        if (idx < N) { g_off[idx] = excl; g_cur[idx] = excl; }
        excl += c[j];
    }
    if (blockIdx.x == 0 && t == 0) g_off[N] = E;
}

// ---------------- K4: payload scatter (counting-sort by dst) ---------------
__global__ void scatter_sort(const int* __restrict__ ei,
                             const float* __restrict__ ew, int E)
{
    int e = blockIdx.x * blockDim.x + threadIdx.x;
    if (e >= E) return;
    int dst = ei[E + e];
    int pos = atomicAdd(&g_cur[dst], 1);
    g_ssrc[pos] = ei[e];
    g_sw[pos]   = ew[e];
}

// ---------------- K5: fused gather + softmax-normalize + elu + residual ----
__global__ __launch_bounds__(256) void gather_fused(float* __restrict__ out, int N)
{
    int node = (blockIdx.x * blockDim.x + threadIdx.x) >> 5;
    int lane = threadIdx.x & 31;
    if (node >= N) return;

    int beg = g_off[node];
    int end = g_off[node + 1];
    int hl = lane & 7;
    float ar = g_ar[node * HH + hl];

    float den = 0.f;
    float acc[8];
    #pragma unroll
    for (int k = 0; k < 8; k++) acc[k] = 0.f;

    #pragma unroll 2
    for (int i = beg; i < end; i++) {
        int src = g_ssrc[i];
        float w = g_sw[i];
        float a = w * (g_al[src * HH + hl] + ar);
        a = fmaxf(a, 0.2f * a);                 // leaky_relu(0.2)
        float ex = __expf(a);
        den += ex;
        float coeff = __shfl_sync(0xffffffffu, ex, lane >> 2);
        const float4* xr = (const float4*)(g_x + (size_t)src * DD + lane * 8);
        float4 v0 = xr[0], v1 = xr[1];
        acc[0] = fmaf(coeff, v0.x, acc[0]);
        acc[1] = fmaf(coeff, v0.y, acc[1]);
        acc[2] = fmaf(coeff, v0.z, acc[2]);
        acc[3] = fmaf(coeff, v0.w, acc[3]);
        acc[4] = fmaf(coeff, v1.x, acc[4]);
        acc[5] = fmaf(coeff, v1.y, acc[5]);
        acc[6] = fmaf(coeff, v1.z, acc[6]);
        acc[7] = fmaf(coeff, v1.w, acc[7]);
    }

    float d = __shfl_sync(0xffffffffu, den, lane >> 2) + 1e-16f;
    float inv = 1.0f / d;

    float* o = out + (size_t)node * DD + lane * 8;   // holds residual
    float4 r0 = *(float4*)o;
    float4 r1 = *(float4*)(o + 4);
    float v;
    v = acc[0] * inv; r0.x += (v > 0.f ? v : expm1f(v));
    v = acc[1] * inv; r0.y += (v > 0.f ? v : expm1f(v));
    v = acc[2] * inv; r0.z += (v > 0.f ? v : expm1f(v));
    v = acc[3] * inv; r0.w += (v > 0.f ? v : expm1f(v));
    v = acc[4] * inv; r1.x += (v > 0.f ? v : expm1f(v));
    v = acc[5] * inv; r1.y += (v > 0.f ? v : expm1f(v));
    v = acc[6] * inv; r1.z += (v > 0.f ? v : expm1f(v));
    v = acc[7] * inv; r1.w += (v > 0.f ? v : expm1f(v));
    *(float4*)o       = r0;
    *(float4*)(o + 4) = r1;
}

// ---------------------------------------------------------------------------
extern "C" void kernel_launch(void* const* d_in, const int* in_sizes, int n_in,
                              void* d_out, int out_size)
{
    const float* feat = (const float*)d_in[0];
    const float* ew   = (const float*)d_in[1];
    const float* Wlin = (const float*)d_in[2];
    const float* attl = (const float*)d_in[3];
    const float* attr = (const float*)d_in[4];
    const float* Wres = (const float*)d_in[5];
    const int*   ei   = (const int*)d_in[6];
    float* out = (float*)d_out;

    int HC = in_sizes[3];            // 256
    int D  = in_sizes[2] / HC;       // 256
    int N  = in_sizes[0] / D;        // 50000
    int E  = in_sizes[1];            // 1600000

    conv_feat<<<(N * (DD / 4) + 255) / 256, 256>>>(feat, N);
    conv_w<<<(NB * DD + 255) / 256, 256>>>(Wlin, Wres);

    dim3 gGemm((N + 127) / 128, 4);
    gemm_tc<<<gGemm, 256>>>(out, N);

    alpha_hist0<<<(N * HH + 255) / 256, 256>>>(attl, attr, N);

    hist_dst<<<(E + 255) / 256, 256>>>(ei, E);

    int nb = (N + SCAN_BLK - 1) / SCAN_BLK;
    scan_phase1<<<nb, 256>>>(N);
    scan_phase2<<<1, 64>>>(nb);
    scan_phase3<<<nb, 256>>>(N, E);

    scatter_sort<<<(E + 255) / 256, 256>>>(ei, ew, E);

    gather_fused<<<(N * 32 + 255) / 256, 256>>>(out, N);
}

// round 11
// speedup vs baseline: 2.4454x; 1.1616x over previous
#include <cuda_runtime.h>
#include <cuda_bf16.h>
#include <math.h>
#include <stdint.h>

// Problem constants (fixed instance): N=50000, E=1600000, D=256, H=8, C=32.
#define DD 256
#define HH 8
#define CC 32
#define MAXN 50176          // 392 * 128
#define MAXE 1600000
#define SCAN_BLK 1024
#define MAXSB 64
#define NB 512              // total output cols (Wlin | Wres)

// ---------------- scratch (device globals; no allocation allowed) ----------
__device__ float g_x[MAXN * DD];
__device__ float g_al[MAXN * HH];
__device__ float g_ar[MAXN * HH];
__device__ int   g_cnt[MAXN + 1];
__device__ int   g_off[MAXN + 1];
__device__ int   g_cur[MAXN];
__device__ int2  g_edge[MAXE];               // dst-sorted payload: (src, w bits)
__device__ int   g_bsum[MAXSB];
__device__ int   g_bpre[MAXSB];
// bf16 hi/lo splits for tensor-core GEMM
__device__ __nv_bfloat16 g_ahi[MAXN * DD];
__device__ __nv_bfloat16 g_alo[MAXN * DD];
__device__ __nv_bfloat16 g_bhi[NB * DD];     // [n][k], k contiguous (W transposed)
__device__ __nv_bfloat16 g_blo[NB * DD];

// ---------------- warp-MMA helpers (baseline PTX, sm_80+) ------------------
__device__ __forceinline__ uint32_t s2u(const void* p) {
    uint32_t a;
    asm("{ .reg .u64 t; cvta.to.shared.u64 t, %1; cvt.u32.u64 %0, t; }"
        : "=r"(a) : "l"(p));
    return a;
}
__device__ __forceinline__ void ldsm4(uint32_t* r, uint32_t addr) {
    asm volatile("ldmatrix.sync.aligned.m8n8.x4.shared.b16 {%0,%1,%2,%3}, [%4];"
                 : "=r"(r[0]), "=r"(r[1]), "=r"(r[2]), "=r"(r[3]) : "r"(addr));
}
__device__ __forceinline__ void mma16816(float* d, const uint32_t* a,
                                         const uint32_t* b) {
    asm volatile(
        "mma.sync.aligned.m16n8k16.row.col.f32.bf16.bf16.f32 "
        "{%0,%1,%2,%3}, {%4,%5,%6,%7}, {%8,%9}, {%0,%1,%2,%3};"
        : "+f"(d[0]), "+f"(d[1]), "+f"(d[2]), "+f"(d[3])
        : "r"(a[0]), "r"(a[1]), "r"(a[2]), "r"(a[3]), "r"(b[0]), "r"(b[1]));
}

// ---------------- K-1a: split feat into bf16 hi/lo -------------------------
__global__ void conv_feat(const float* __restrict__ feat, int N)
{
    int i = blockIdx.x * blockDim.x + threadIdx.x;       // float4 index
    if (i >= N * (DD / 4)) return;
    float4 v = ((const float4*)feat)[i];
    __nv_bfloat16 h0 = __float2bfloat16(v.x);
    __nv_bfloat16 h1 = __float2bfloat16(v.y);
    __nv_bfloat16 h2 = __float2bfloat16(v.z);
    __nv_bfloat16 h3 = __float2bfloat16(v.w);
    __nv_bfloat16 l0 = __float2bfloat16(v.x - __bfloat162float(h0));
    __nv_bfloat16 l1 = __float2bfloat16(v.y - __bfloat162float(h1));
    __nv_bfloat16 l2 = __float2bfloat16(v.z - __bfloat162float(h2));
    __nv_bfloat16 l3 = __float2bfloat16(v.w - __bfloat162float(h3));
    ((__nv_bfloat162*)g_ahi)[i * 2]     = __nv_bfloat162(h0, h1);
    ((__nv_bfloat162*)g_ahi)[i * 2 + 1] = __nv_bfloat162(h2, h3);
    ((__nv_bfloat162*)g_alo)[i * 2]     = __nv_bfloat162(l0, l1);
    ((__nv_bfloat162*)g_alo)[i * 2 + 1] = __nv_bfloat162(l2, l3);
}

// ---------------- K-1b: transpose+split W into B [n][k] bf16 hi/lo ---------
__global__ void conv_w(const float* __restrict__ Wlin, const float* __restrict__ Wres)
{
    int idx = blockIdx.x * blockDim.x + threadIdx.x;     // n*256 + k
    if (idx >= NB * DD) return;
    int n = idx >> 8, k = idx & 255;
    float v = (n < 256) ? Wlin[k * 256 + n] : Wres[k * 256 + (n - 256)];
    __nv_bfloat16 h = __float2bfloat16(v);
    __nv_bfloat16 l = __float2bfloat16(v - __bfloat162float(h));
    g_bhi[idx] = h;
    g_blo[idx] = l;
}

// ---------------- K0: HMMA dual GEMM (mma.sync, 3-term bf16 split) ---------
// CTA: 128x128 output, 256 thr (8 warps, 4m x 2n), BK=32, smem rows 80B pad.
#define LDS 80          // bytes per smem row (40 halves) — conflict-free ldmatrix
__global__ __launch_bounds__(256) void gemm_tc(float* __restrict__ Res, int M)
{
    __shared__ __align__(16) char smAh[128 * LDS];
    __shared__ __align__(16) char smAl[128 * LDS];
    __shared__ __align__(16) char smBh[128 * LDS];
    __shared__ __align__(16) char smBl[128 * LDS];

    int tid = threadIdx.x;
    int wid = tid >> 5, lane = tid & 31;
    int wm = wid >> 1;          // 0..3 -> m offset wm*32
    int wn = wid & 1;           // 0..1 -> n offset wn*64
    int bm = blockIdx.x, bn = blockIdx.y;

    uint32_t aHi = s2u(smAh), aLo = s2u(smAl);
    uint32_t bHi = s2u(smBh), bLo = s2u(smBl);

    // per-lane ldmatrix offsets
    uint32_t offA = (uint32_t)((lane & 15) * LDS + (lane >> 4) * 16);
    uint32_t offB = (uint32_t)(((lane & 7) + ((lane >> 4) & 1) * 8) * LDS +
                               ((lane >> 3) & 1) * 16);

    const __nv_bfloat16* gAh = g_ahi + (size_t)bm * 128 * DD;
    const __nv_bfloat16* gAl = g_alo + (size_t)bm * 128 * DD;
    const __nv_bfloat16* gBh = g_bhi + (size_t)bn * 128 * DD;
    const __nv_bfloat16* gBl = g_blo + (size_t)bn * 128 * DD;

    float acc[2][8][4];
    #pragma unroll
    for (int mt = 0; mt < 2; mt++)
        #pragma unroll
        for (int nt = 0; nt < 8; nt++)
            #pragma unroll
            for (int j = 0; j < 4; j++) acc[mt][nt][j] = 0.f;

    for (int kc = 0; kc < 8; kc++) {            // K chunks of 32
        const __nv_bfloat16* srcs[4] = {gAh, gAl, gBh, gBl};
        char* dsts[4] = {smAh, smAl, smBh, smBl};
        #pragma unroll
        for (int m = 0; m < 4; m++) {
            const __nv_bfloat16* P = srcs[m] + kc * 32;
            #pragma unroll
            for (int i = 0; i < 2; i++) {
                int t2 = tid * 2 + i;           // 0..511
                int row = t2 >> 2, seg = t2 & 3;
                uint4 v = *(const uint4*)(P + (size_t)row * DD + seg * 8);
                *(uint4*)(dsts[m] + row * LDS + seg * 16) = v;
            }
        }
        __syncthreads();

        #pragma unroll
        for (int ks = 0; ks < 2; ks++) {        // two k=16 steps
            uint32_t kb = ks * 32;
            uint32_t ah[2][4], al[2][4];
            #pragma unroll
            for (int mt = 0; mt < 2; mt++) {
                uint32_t ro = (uint32_t)((wm * 32 + mt * 16) * LDS) + offA + kb;
                ldsm4(ah[mt], aHi + ro);
                ldsm4(al[mt], aLo + ro);
            }
            uint32_t bh[4][4], bl[4][4];
            #pragma unroll
            for (int np = 0; np < 4; np++) {
                uint32_t ro = (uint32_t)((wn * 64 + np * 16) * LDS) + offB + kb;
                ldsm4(bh[np], bHi + ro);
                ldsm4(bl[np], bLo + ro);
            }
            #pragma unroll
            for (int mt = 0; mt < 2; mt++)
                #pragma unroll
                for (int nt = 0; nt < 8; nt++) {
                    float* d = acc[mt][nt];
                    const uint32_t* Bh2 = &bh[nt >> 1][(nt & 1) * 2];
                    const uint32_t* Bl2 = &bl[nt >> 1][(nt & 1) * 2];
                    mma16816(d, ah[mt], Bh2);   // hi*hi
                    mma16816(d, ah[mt], Bl2);   // hi*lo
                    mma16816(d, al[mt], Bh2);   // lo*hi
                }
        }
        __syncthreads();
    }

    // epilogue: write D fragments to g_x (bn 0,1) or Res (bn 2,3)
    #pragma unroll
    for (int mt = 0; mt < 2; mt++) {
        int row0 = bm * 128 + wm * 32 + mt * 16 + (lane >> 2);
        #pragma unroll
        for (int half = 0; half < 2; half++) {
            int row = row0 + half * 8;
            if (row < M) {
                float* base = (bn < 2)
                    ? g_x + (size_t)row * DD + bn * 128
                    : Res + (size_t)row * DD + (bn - 2) * 128;
                #pragma unroll
                for (int nt = 0; nt < 8; nt++) {
                    float2 v = make_float2(acc[mt][nt][half * 2],
                                           acc[mt][nt][half * 2 + 1]);
                    *(float2*)(base + wn * 64 + nt * 8 + (lane & 3) * 2) = v;
                }
            }
        }
    }
}

// ---------------- K1: warp-per-node alpha_l/alpha_r + zero histogram -------
// Lane l reads x[node, l*8 .. l*8+8) (coalesced float4); all 8 elements lie
// in head l>>2. Quad-reduce gives per-head dot products.
__global__ __launch_bounds__(256) void alpha_hist0(
    const float* __restrict__ attl, const float* __restrict__ attr, int N)
{
    __shared__ float sl[DD], sr[DD];
    if (threadIdx.x < DD) {
        sl[threadIdx.x] = attl[threadIdx.x];
        sr[threadIdx.x] = attr[threadIdx.x];
    }
    __syncthreads();
    int gtid = blockIdx.x * blockDim.x + threadIdx.x;
    if (gtid <= N) g_cnt[gtid] = 0;

    int node = gtid >> 5;
    int lane = threadIdx.x & 31;
    if (node >= N) return;

    const float4* xr = (const float4*)(g_x + (size_t)node * DD + lane * 8);
    float4 v0 = xr[0], v1 = xr[1];
    const float* al = sl + lane * 8;
    const float* ar = sr + lane * 8;
    float sa = v0.x * al[0] + v0.y * al[1] + v0.z * al[2] + v0.w * al[3]
             + v1.x * al[4] + v1.y * al[5] + v1.z * al[6] + v1.w * al[7];
    float sb = v0.x * ar[0] + v0.y * ar[1] + v0.z * ar[2] + v0.w * ar[3]
             + v1.x * ar[4] + v1.y * ar[5] + v1.z * ar[6] + v1.w * ar[7];
    // reduce within quad (lanes sharing lane>>2 == head)
    sa += __shfl_xor_sync(0xffffffffu, sa, 1);
    sa += __shfl_xor_sync(0xffffffffu, sa, 2);
    sb += __shfl_xor_sync(0xffffffffu, sb, 1);
    sb += __shfl_xor_sync(0xffffffffu, sb, 2);
    if ((lane & 3) == 0) {
        int h = lane >> 2;
        g_al[node * HH + h] = sa;
        g_ar[node * HH + h] = sb;
    }
}

// ---------------- K2: histogram of destination degrees ---------------------
__global__ void hist_dst(const int* __restrict__ ei, int E)
{
    int e = blockIdx.x * blockDim.x + threadIdx.x;
    if (e >= E) return;
    atomicAdd(&g_cnt[ei[E + e]], 1);
}

// ---------------- K3a/b/c: 3-phase exclusive scan --------------------------
__global__ void scan_phase1(int N)
{
    __shared__ int wsum[8];
    int t = threadIdx.x;
    int base = blockIdx.x * SCAN_BLK + t * 4;
    int s = 0;
    #pragma unroll
    for (int j = 0; j < 4; j++) s += (base + j < N) ? g_cnt[base + j] : 0;
    #pragma unroll
    for (int off = 16; off; off >>= 1) s += __shfl_xor_sync(0xffffffffu, s, off);
    if ((t & 31) == 0) wsum[t >> 5] = s;
    __syncthreads();
    if (t == 0) {
        int tot = 0;
        #pragma unroll
        for (int i = 0; i < 8; i++) tot += wsum[i];
        g_bsum[blockIdx.x] = tot;
    }
}
__global__ void scan_phase2(int nb)
{
    __shared__ int wt[2];
    int t = threadIdx.x;
    int lane = t & 31, wid = t >> 5;
    int mine = (t < nb) ? g_bsum[t] : 0;
    int v = mine;
    #pragma unroll
    for (int off = 1; off < 32; off <<= 1) {
        int u = __shfl_up_sync(0xffffffffu, v, off);
        if (lane >= off) v += u;
    }
    if (lane == 31) wt[wid] = v;
    __syncthreads();
    if (wid == 1) v += wt[0];
    if (t < nb) g_bpre[t] = v - mine;
}
__global__ void scan_phase3(int N, int E)
{
    __shared__ int warp_tot[8];
    int t = threadIdx.x;
    int lane = t & 31, wid = t >> 5;
    int base = blockIdx.x * SCAN_BLK + t * 4;
    int c[4];
    #pragma unroll
    for (int j = 0; j < 4; j++) c[j] = (base + j < N) ? g_cnt[base + j] : 0;
    int tsum = c[0] + c[1] + c[2] + c[3];
    int v = tsum;
    #pragma unroll
    for (int off = 1; off < 32; off <<= 1) {
        int u = __shfl_up_sync(0xffffffffu, v, off);
        if (lane >= off) v += u;
    }
    if (lane == 31) warp_tot[wid] = v;
    __syncthreads();
    if (wid == 0) {
        int wv = (lane < 8) ? warp_tot[lane] : 0;
        #pragma unroll
        for (int off = 1; off < 8; off <<= 1) {
            int u = __shfl_up_sync(0xffffffffu, wv, off);
            if (lane >= off) wv += u;
        }
        if (lane < 8) warp_tot[lane] = wv;
    }
    __syncthreads();
    int excl = v - tsum + ((wid > 0) ? warp_tot[wid - 1] : 0) + g_bpre[blockIdx.x];
    #pragma unroll
    for (int j = 0; j < 4; j++) {
        int idx = base + j;
        if (idx < N) { g_off[idx] = excl; g_cur[idx] = excl; }
        excl += c[j];
    }
    if (blockIdx.x == 0 && t == 0) g_off[N] = E;
}

// ---------------- K4: payload scatter (counting-sort by dst) ---------------
__global__ void scatter_sort(const int* __restrict__ ei,
                             const float* __restrict__ ew, int E)
{
    int e = blockIdx.x * blockDim.x + threadIdx.x;
    if (e >= E) return;
    int dst = ei[E + e];
    int pos = atomicAdd(&g_cur[dst], 1);
    g_edge[pos] = make_int2(ei[e], __float_as_int(ew[e]));
}

// ---------------- K5: fused gather + softmax-normalize + elu + residual ----
__global__ __launch_bounds__(256) void gather_fused(float* __restrict__ out, int N)
{
    int node = (blockIdx.x * blockDim.x + threadIdx.x) >> 5;
    int lane = threadIdx.x & 31;
    if (node >= N) return;

    int beg = g_off[node];
    int end = g_off[node + 1];
    int hl = lane & 7;
    float ar = g_ar[node * HH + hl];

    float den = 0.f;
    float acc[8];
    #pragma unroll
    for (int k = 0; k < 8; k++) acc[k] = 0.f;

    #pragma unroll 2
    for (int i = beg; i < end; i++) {
        int2 p = g_edge[i];
        int src = p.x;
        float w = __int_as_float(p.y);
        float a = w * (g_al[src * HH + hl] + ar);
        a = fmaxf(a, 0.2f * a);                 // leaky_relu(0.2)
        float ex = __expf(a);
        den += ex;
        float coeff = __shfl_sync(0xffffffffu, ex, lane >> 2);
        const float4* xr = (const float4*)(g_x + (size_t)src * DD + lane * 8);
        float4 v0 = xr[0], v1 = xr[1];
        acc[0] = fmaf(coeff, v0.x, acc[0]);
        acc[1] = fmaf(coeff, v0.y, acc[1]);
        acc[2] = fmaf(coeff, v0.z, acc[2]);
        acc[3] = fmaf(coeff, v0.w, acc[3]);
        acc[4] = fmaf(coeff, v1.x, acc[4]);
        acc[5] = fmaf(coeff, v1.y, acc[5]);
        acc[6] = fmaf(coeff, v1.z, acc[6]);
        acc[7] = fmaf(coeff, v1.w, acc[7]);
    }

    float d = __shfl_sync(0xffffffffu, den, lane >> 2) + 1e-16f;
    float inv = 1.0f / d;

    float* o = out + (size_t)node * DD + lane * 8;   // holds residual
    float4 r0 = *(float4*)o;
    float4 r1 = *(float4*)(o + 4);
    float v;
    v = acc[0] * inv; r0.x += (v > 0.f ? v : expm1f(v));
    v = acc[1] * inv; r0.y += (v > 0.f ? v : expm1f(v));
    v = acc[2] * inv; r0.z += (v > 0.f ? v : expm1f(v));
    v = acc[3] * inv; r0.w += (v > 0.f ? v : expm1f(v));
    v = acc[4] * inv; r1.x += (v > 0.f ? v : expm1f(v));
    v = acc[5] * inv; r1.y += (v > 0.f ? v : expm1f(v));
    v = acc[6] * inv; r1.z += (v > 0.f ? v : expm1f(v));
    v = acc[7] * inv; r1.w += (v > 0.f ? v : expm1f(v));
    *(float4*)o       = r0;
    *(float4*)(o + 4) = r1;
}

// ---------------------------------------------------------------------------
extern "C" void kernel_launch(void* const* d_in, const int* in_sizes, int n_in,
                              void* d_out, int out_size)
{
    const float* feat = (const float*)d_in[0];
    const float* ew   = (const float*)d_in[1];
    const float* Wlin = (const float*)d_in[2];
    const float* attl = (const float*)d_in[3];
    const float* attr = (const float*)d_in[4];
    const float* Wres = (const float*)d_in[5];
    const int*   ei   = (const int*)d_in[6];
    float* out = (float*)d_out;

    int HC = in_sizes[3];            // 256
    int D  = in_sizes[2] / HC;       // 256
    int N  = in_sizes[0] / D;        // 50000
    int E  = in_sizes[1];            // 1600000

    conv_feat<<<(N * (DD / 4) + 255) / 256, 256>>>(feat, N);
    conv_w<<<(NB * DD + 255) / 256, 256>>>(Wlin, Wres);

    dim3 gGemm((N + 127) / 128, 4);
    gemm_tc<<<gGemm, 256>>>(out, N);

    alpha_hist0<<<(N * 32 + 255) / 256, 256>>>(attl, attr, N);

    hist_dst<<<(E + 255) / 256, 256>>>(ei, E);

    int nb = (N + SCAN_BLK - 1) / SCAN_BLK;
    scan_phase1<<<nb, 256>>>(N);
    scan_phase2<<<1, 64>>>(nb);
    scan_phase3<<<nb, 256>>>(N, E);

    scatter_sort<<<(E + 255) / 256, 256>>>(ei, ew, E);

    gather_fused<<<(N * 32 + 255) / 256, 256>>>(out, N);
}

// round 12
// speedup vs baseline: 2.6386x; 1.0790x over previous
#include <cuda_runtime.h>
#include <cuda_bf16.h>
#include <math.h>
#include <stdint.h>

// Problem constants (fixed instance): N=50000, E=1600000, D=256, H=8, C=32.
#define DD 256
#define HH 8
#define CC 32
#define MAXN 50176          // 392 * 128
#define MAXE 1600000
#define SCAN_BLK 1024
#define MAXSB 64
#define NB 512              // total output cols (Wlin | Wres)

// ---------------- scratch (device globals; no allocation allowed) ----------
__device__ float g_x[MAXN * DD];
__device__ float g_al[MAXN * HH];
__device__ float g_ar[MAXN * HH];
__device__ int   g_cnt[MAXN + 1];
__device__ int   g_off[MAXN + 1];
__device__ int   g_cur[MAXN];
__device__ int2  g_edge[MAXE];               // dst-sorted payload: (src, w bits)
__device__ int   g_bsum[MAXSB];
__device__ int   g_bpre[MAXSB];
// bf16 hi/lo splits for tensor-core GEMM
__device__ __nv_bfloat16 g_ahi[MAXN * DD];
__device__ __nv_bfloat16 g_alo[MAXN * DD];
__device__ __nv_bfloat16 g_bhi[NB * DD];     // [n][k], k contiguous (W transposed)
__device__ __nv_bfloat16 g_blo[NB * DD];

// ---------------- warp-MMA helpers (baseline PTX, sm_80+) ------------------
__device__ __forceinline__ uint32_t s2u(const void* p) {
    uint32_t a;
    asm("{ .reg .u64 t; cvta.to.shared.u64 t, %1; cvt.u32.u64 %0, t; }"
        : "=r"(a) : "l"(p));
    return a;
}
__device__ __forceinline__ void ldsm4(uint32_t* r, uint32_t addr) {
    asm volatile("ldmatrix.sync.aligned.m8n8.x4.shared.b16 {%0,%1,%2,%3}, [%4];"
                 : "=r"(r[0]), "=r"(r[1]), "=r"(r[2]), "=r"(r[3]) : "r"(addr));
}
__device__ __forceinline__ void mma16816(float* d, const uint32_t* a,
                                         const uint32_t* b) {
    asm volatile(
        "mma.sync.aligned.m16n8k16.row.col.f32.bf16.bf16.f32 "
        "{%0,%1,%2,%3}, {%4,%5,%6,%7}, {%8,%9}, {%0,%1,%2,%3};"
        : "+f"(d[0]), "+f"(d[1]), "+f"(d[2]), "+f"(d[3])
        : "r"(a[0]), "r"(a[1]), "r"(a[2]), "r"(a[3]), "r"(b[0]), "r"(b[1]));
}

// ---------------- K-1a: split feat into bf16 hi/lo -------------------------
__global__ void conv_feat(const float* __restrict__ feat, int N)
{
    int i = blockIdx.x * blockDim.x + threadIdx.x;       // float4 index
    if (i >= N * (DD / 4)) return;
    float4 v = ((const float4*)feat)[i];
    __nv_bfloat16 h0 = __float2bfloat16(v.x);
    __nv_bfloat16 h1 = __float2bfloat16(v.y);
    __nv_bfloat16 h2 = __float2bfloat16(v.z);
    __nv_bfloat16 h3 = __float2bfloat16(v.w);
    __nv_bfloat16 l0 = __float2bfloat16(v.x - __bfloat162float(h0));
    __nv_bfloat16 l1 = __float2bfloat16(v.y - __bfloat162float(h1));
    __nv_bfloat16 l2 = __float2bfloat16(v.z - __bfloat162float(h2));
    __nv_bfloat16 l3 = __float2bfloat16(v.w - __bfloat162float(h3));
    ((__nv_bfloat162*)g_ahi)[i * 2]     = __nv_bfloat162(h0, h1);
    ((__nv_bfloat162*)g_ahi)[i * 2 + 1] = __nv_bfloat162(h2, h3);
    ((__nv_bfloat162*)g_alo)[i * 2]     = __nv_bfloat162(l0, l1);
    ((__nv_bfloat162*)g_alo)[i * 2 + 1] = __nv_bfloat162(l2, l3);
}

// ---------------- K-1b: transpose+split W into B [n][k] bf16 hi/lo ---------
__global__ void conv_w(const float* __restrict__ Wlin, const float* __restrict__ Wres)
{
    int idx = blockIdx.x * blockDim.x + threadIdx.x;     // n*256 + k
    if (idx >= NB * DD) return;
    int n = idx >> 8, k = idx & 255;
    float v = (n < 256) ? Wlin[k * 256 + n] : Wres[k * 256 + (n - 256)];
    __nv_bfloat16 h = __float2bfloat16(v);
    __nv_bfloat16 l = __float2bfloat16(v - __bfloat162float(h));
    g_bhi[idx] = h;
    g_blo[idx] = l;
}

// ---------------- K0: HMMA dual GEMM (mma.sync, 3-term bf16 split) ---------
// CTA: 128x128 output, 256 thr (8 warps, 4m x 2n), BK=32, smem rows 80B pad.
#define LDS 80          // bytes per smem row (40 halves) — conflict-free ldmatrix
__global__ __launch_bounds__(256) void gemm_tc(float* __restrict__ Res, int M)
{
    __shared__ __align__(16) char smAh[128 * LDS];
    __shared__ __align__(16) char smAl[128 * LDS];
    __shared__ __align__(16) char smBh[128 * LDS];
    __shared__ __align__(16) char smBl[128 * LDS];

    int tid = threadIdx.x;
    int wid = tid >> 5, lane = tid & 31;
    int wm = wid >> 1;          // 0..3 -> m offset wm*32
    int wn = wid & 1;           // 0..1 -> n offset wn*64
    int bm = blockIdx.x, bn = blockIdx.y;

    uint32_t aHi = s2u(smAh), aLo = s2u(smAl);
    uint32_t bHi = s2u(smBh), bLo = s2u(smBl);

    // per-lane ldmatrix offsets
    uint32_t offA = (uint32_t)((lane & 15) * LDS + (lane >> 4) * 16);
    uint32_t offB = (uint32_t)(((lane & 7) + ((lane >> 4) & 1) * 8) * LDS +
                               ((lane >> 3) & 1) * 16);

    const __nv_bfloat16* gAh = g_ahi + (size_t)bm * 128 * DD;
    const __nv_bfloat16* gAl = g_alo + (size_t)bm * 128 * DD;
    const __nv_bfloat16* gBh = g_bhi + (size_t)bn * 128 * DD;
    const __nv_bfloat16* gBl = g_blo + (size_t)bn * 128 * DD;

    float acc[2][8][4];
    #pragma unroll
    for (int mt = 0; mt < 2; mt++)
        #pragma unroll
        for (int nt = 0; nt < 8; nt++)
            #pragma unroll
            for (int j = 0; j < 4; j++) acc[mt][nt][j] = 0.f;

    for (int kc = 0; kc < 8; kc++) {            // K chunks of 32
        const __nv_bfloat16* srcs[4] = {gAh, gAl, gBh, gBl};
        char* dsts[4] = {smAh, smAl, smBh, smBl};
        #pragma unroll
        for (int m = 0; m < 4; m++) {
            const __nv_bfloat16* P = srcs[m] + kc * 32;
            #pragma unroll
            for (int i = 0; i < 2; i++) {
                int t2 = tid * 2 + i;           // 0..511
                int row = t2 >> 2, seg = t2 & 3;
                uint4 v = *(const uint4*)(P + (size_t)row * DD + seg * 8);
                *(uint4*)(dsts[m] + row * LDS + seg * 16) = v;
            }
        }
        __syncthreads();

        #pragma unroll
        for (int ks = 0; ks < 2; ks++) {        // two k=16 steps
            uint32_t kb = ks * 32;
            uint32_t ah[2][4], al[2][4];
            #pragma unroll
            for (int mt = 0; mt < 2; mt++) {
                uint32_t ro = (uint32_t)((wm * 32 + mt * 16) * LDS) + offA + kb;
                ldsm4(ah[mt], aHi + ro);
                ldsm4(al[mt], aLo + ro);
            }
            uint32_t bh[4][4], bl[4][4];
            #pragma unroll
            for (int np = 0; np < 4; np++) {
                uint32_t ro = (uint32_t)((wn * 64 + np * 16) * LDS) + offB + kb;
                ldsm4(bh[np], bHi + ro);
                ldsm4(bl[np], bLo + ro);
            }
            #pragma unroll
            for (int mt = 0; mt < 2; mt++)
                #pragma unroll
                for (int nt = 0; nt < 8; nt++) {
                    float* d = acc[mt][nt];
                    const uint32_t* Bh2 = &bh[nt >> 1][(nt & 1) * 2];
                    const uint32_t* Bl2 = &bl[nt >> 1][(nt & 1) * 2];
                    mma16816(d, ah[mt], Bh2);   // hi*hi
                    mma16816(d, ah[mt], Bl2);   // hi*lo
                    mma16816(d, al[mt], Bh2);   // lo*hi
                }
        }
        __syncthreads();
    }

    // epilogue: write D fragments to g_x (bn 0,1) or Res (bn 2,3)
    #pragma unroll
    for (int mt = 0; mt < 2; mt++) {
        int row0 = bm * 128 + wm * 32 + mt * 16 + (lane >> 2);
        #pragma unroll
        for (int half = 0; half < 2; half++) {
            int row = row0 + half * 8;
            if (row < M) {
                float* base = (bn < 2)
                    ? g_x + (size_t)row * DD + bn * 128
                    : Res + (size_t)row * DD + (bn - 2) * 128;
                #pragma unroll
                for (int nt = 0; nt < 8; nt++) {
                    float2 v = make_float2(acc[mt][nt][half * 2],
                                           acc[mt][nt][half * 2 + 1]);
                    *(float2*)(base + wn * 64 + nt * 8 + (lane & 3) * 2) = v;
                }
            }
        }
    }
}

// ---------------- K1: warp-per-node alpha_l/alpha_r ------------------------
__global__ __launch_bounds__(256) void alpha_k(
    const float* __restrict__ attl, const float* __restrict__ attr, int N)
{
    __shared__ float sl[DD], sr[DD];
    if (threadIdx.x < DD) {
        sl[threadIdx.x] = attl[threadIdx.x];
        sr[threadIdx.x] = attr[threadIdx.x];
    }
    __syncthreads();
    int gtid = blockIdx.x * blockDim.x + threadIdx.x;
    int node = gtid >> 5;
    int lane = threadIdx.x & 31;
    if (node >= N) return;

    const float4* xr = (const float4*)(g_x + (size_t)node * DD + lane * 8);
    float4 v0 = xr[0], v1 = xr[1];
    const float* al = sl + lane * 8;
    const float* ar = sr + lane * 8;
    float sa = v0.x * al[0] + v0.y * al[1] + v0.z * al[2] + v0.w * al[3]
             + v1.x * al[4] + v1.y * al[5] + v1.z * al[6] + v1.w * al[7];
    float sb = v0.x * ar[0] + v0.y * ar[1] + v0.z * ar[2] + v0.w * ar[3]
             + v1.x * ar[4] + v1.y * ar[5] + v1.z * ar[6] + v1.w * ar[7];
    sa += __shfl_xor_sync(0xffffffffu, sa, 1);
    sa += __shfl_xor_sync(0xffffffffu, sa, 2);
    sb += __shfl_xor_sync(0xffffffffu, sb, 1);
    sb += __shfl_xor_sync(0xffffffffu, sb, 2);
    if ((lane & 3) == 0) {
        int h = lane >> 2;
        g_al[node * HH + h] = sa;
        g_ar[node * HH + h] = sb;
    }
}

// ---------------- K2a: zero histogram (head of edge stream) ----------------
__global__ void zero_cnt(int N)
{
    int i = blockIdx.x * blockDim.x + threadIdx.x;
    if (i <= N) g_cnt[i] = 0;
}

// ---------------- K2b: histogram of destination degrees --------------------
__global__ void hist_dst(const int* __restrict__ ei, int E)
{
    int e = blockIdx.x * blockDim.x + threadIdx.x;
    if (e >= E) return;
    atomicAdd(&g_cnt[ei[E + e]], 1);
}

// ---------------- K3a/b/c: 3-phase exclusive scan --------------------------
__global__ void scan_phase1(int N)
{
    __shared__ int wsum[8];
    int t = threadIdx.x;
    int base = blockIdx.x * SCAN_BLK + t * 4;
    int s = 0;
    #pragma unroll
    for (int j = 0; j < 4; j++) s += (base + j < N) ? g_cnt[base + j] : 0;
    #pragma unroll
    for (int off = 16; off; off >>= 1) s += __shfl_xor_sync(0xffffffffu, s, off);
    if ((t & 31) == 0) wsum[t >> 5] = s;
    __syncthreads();
    if (t == 0) {
        int tot = 0;
        #pragma unroll
        for (int i = 0; i < 8; i++) tot += wsum[i];
        g_bsum[blockIdx.x] = tot;
    }
}
__global__ void scan_phase2(int nb)
{
    __shared__ int wt[2];
    int t = threadIdx.x;
    int lane = t & 31, wid = t >> 5;
    int mine = (t < nb) ? g_bsum[t] : 0;
    int v = mine;
    #pragma unroll
    for (int off = 1; off < 32; off <<= 1) {
        int u = __shfl_up_sync(0xffffffffu, v, off);
        if (lane >= off) v += u;
    }
    if (lane == 31) wt[wid] = v;
    __syncthreads();
    if (wid == 1) v += wt[0];
    if (t < nb) g_bpre[t] = v - mine;
}
__global__ void scan_phase3(int N, int E)
{
    __shared__ int warp_tot[8];
    int t = threadIdx.x;
    int lane = t & 31, wid = t >> 5;
    int base = blockIdx.x * SCAN_BLK + t * 4;
    int c[4];
    #pragma unroll
    for (int j = 0; j < 4; j++) c[j] = (base + j < N) ? g_cnt[base + j] : 0;
    int tsum = c[0] + c[1] + c[2] + c[3];
    int v = tsum;
    #pragma unroll
    for (int off = 1; off < 32; off <<= 1) {
        int u = __shfl_up_sync(0xffffffffu, v, off);
        if (lane >= off) v += u;
    }
    if (lane == 31) warp_tot[wid] = v;
    __syncthreads();
    if (wid == 0) {
        int wv = (lane < 8) ? warp_tot[lane] : 0;
        #pragma unroll
        for (int off = 1; off < 8; off <<= 1) {
            int u = __shfl_up_sync(0xffffffffu, wv, off);
            if (lane >= off) wv += u;
        }
        if (lane < 8) warp_tot[lane] = wv;
    }
    __syncthreads();
    int excl = v - tsum + ((wid > 0) ? warp_tot[wid - 1] : 0) + g_bpre[blockIdx.x];
    #pragma unroll
    for (int j = 0; j < 4; j++) {
        int idx = base + j;
        if (idx < N) { g_off[idx] = excl; g_cur[idx] = excl; }
        excl += c[j];
    }
    if (blockIdx.x == 0 && t == 0) g_off[N] = E;
}

// ---------------- K4: payload scatter (counting-sort by dst) ---------------
__global__ void scatter_sort(const int* __restrict__ ei,
                             const float* __restrict__ ew, int E)
{
    int e = blockIdx.x * blockDim.x + threadIdx.x;
    if (e >= E) return;
    int dst = ei[E + e];
    int pos = atomicAdd(&g_cur[dst], 1);
    g_edge[pos] = make_int2(ei[e], __float_as_int(ew[e]));
}

// ---------------- K5: fused gather + softmax-normalize + elu + residual ----
__global__ __launch_bounds__(256) void gather_fused(float* __restrict__ out, int N)
{
    int node = (blockIdx.x * blockDim.x + threadIdx.x) >> 5;
    int lane = threadIdx.x & 31;
    if (node >= N) return;

    int beg = g_off[node];
    int end = g_off[node + 1];
    int hl = lane & 7;
    float ar = g_ar[node * HH + hl];

    float den = 0.f;
    float acc[8];
    #pragma unroll
    for (int k = 0; k < 8; k++) acc[k] = 0.f;

    #pragma unroll 2
    for (int i = beg; i < end; i++) {
        int2 p = g_edge[i];
        int src = p.x;
        float w = __int_as_float(p.y);
        float a = w * (g_al[src * HH + hl] + ar);
        a = fmaxf(a, 0.2f * a);                 // leaky_relu(0.2)
        float ex = __expf(a);
        den += ex;
        float coeff = __shfl_sync(0xffffffffu, ex, lane >> 2);
        const float4* xr = (const float4*)(g_x + (size_t)src * DD + lane * 8);
        float4 v0 = xr[0], v1 = xr[1];
        acc[0] = fmaf(coeff, v0.x, acc[0]);
        acc[1] = fmaf(coeff, v0.y, acc[1]);
        acc[2] = fmaf(coeff, v0.z, acc[2]);
        acc[3] = fmaf(coeff, v0.w, acc[3]);
        acc[4] = fmaf(coeff, v1.x, acc[4]);
        acc[5] = fmaf(coeff, v1.y, acc[5]);
        acc[6] = fmaf(coeff, v1.z, acc[6]);
        acc[7] = fmaf(coeff, v1.w, acc[7]);
    }

    float d = __shfl_sync(0xffffffffu, den, lane >> 2) + 1e-16f;
    float inv = 1.0f / d;

    float* o = out + (size_t)node * DD + lane * 8;   // holds residual
    float4 r0 = *(float4*)o;
    float4 r1 = *(float4*)(o + 4);
    float v;
    v = acc[0] * inv; r0.x += (v > 0.f ? v : expm1f(v));
    v = acc[1] * inv; r0.y += (v > 0.f ? v : expm1f(v));
    v = acc[2] * inv; r0.z += (v > 0.f ? v : expm1f(v));
    v = acc[3] * inv; r0.w += (v > 0.f ? v : expm1f(v));
    v = acc[4] * inv; r1.x += (v > 0.f ? v : expm1f(v));
    v = acc[5] * inv; r1.y += (v > 0.f ? v : expm1f(v));
    v = acc[6] * inv; r1.z += (v > 0.f ? v : expm1f(v));
    v = acc[7] * inv; r1.w += (v > 0.f ? v : expm1f(v));
    *(float4*)o       = r0;
    *(float4*)(o + 4) = r1;
}

// ---------------------------------------------------------------------------
// Stream fork/join: edge-preprocessing chain (zero/hist/scan/scatter) depends
// only on edge_index/edge_weight and runs concurrently with the conv/GEMM/
// alpha chain. Streams/events are created lazily on the first (uncaptured)
// correctness call and reused during graph capture.
extern "C" void kernel_launch(void* const* d_in, const int* in_sizes, int n_in,
                              void* d_out, int out_size)
{
    const float* feat = (const float*)d_in[0];
    const float* ew   = (const float*)d_in[1];
    const float* Wlin = (const float*)d_in[2];
    const float* attl = (const float*)d_in[3];
    const float* attr = (const float*)d_in[4];
    const float* Wres = (const float*)d_in[5];
    const int*   ei   = (const int*)d_in[6];
    float* out = (float*)d_out;

    int HC = in_sizes[3];            // 256
    int D  = in_sizes[2] / HC;       // 256
    int N  = in_sizes[0] / D;        // 50000
    int E  = in_sizes[1];            // 1600000

    static cudaStream_t s2 = nullptr;
    static cudaEvent_t evFork = nullptr, evJoin = nullptr;
    if (!s2) {
        cudaStreamCreateWithFlags(&s2, cudaStreamNonBlocking);
        cudaEventCreateWithFlags(&evFork, cudaEventDisableTiming);
        cudaEventCreateWithFlags(&evJoin, cudaEventDisableTiming);
    }

    // fork: edge chain on s2
    cudaEventRecord(evFork, 0);
    cudaStreamWaitEvent(s2, evFork, 0);

    zero_cnt<<<(N + 256) / 256, 256, 0, s2>>>(N);
    hist_dst<<<(E + 255) / 256, 256, 0, s2>>>(ei, E);
    int nb = (N + SCAN_BLK - 1) / SCAN_BLK;
    scan_phase1<<<nb, 256, 0, s2>>>(N);
    scan_phase2<<<1, 64, 0, s2>>>(nb);
    scan_phase3<<<nb, 256, 0, s2>>>(N, E);
    scatter_sort<<<(E + 255) / 256, 256, 0, s2>>>(ei, ew, E);
    cudaEventRecord(evJoin, s2);

    // main chain on default stream
    conv_feat<<<(N * (DD / 4) + 255) / 256, 256>>>(feat, N);
    conv_w<<<(NB * DD + 255) / 256, 256>>>(Wlin, Wres);

    dim3 gGemm((N + 127) / 128, 4);
    gemm_tc<<<gGemm, 256>>>(out, N);

    alpha_k<<<(N * 32 + 255) / 256, 256>>>(attl, attr, N);

    // join: gather needs both chains
    cudaStreamWaitEvent(0, evJoin, 0);
    gather_fused<<<(N * 32 + 255) / 256, 256>>>(out, N);
}

// round 13
// speedup vs baseline: 3.0280x; 1.1476x over previous
#include <cuda_runtime.h>
#include <cuda_bf16.h>
#include <cuda_fp16.h>
#include <math.h>
#include <stdint.h>

// Problem constants (fixed instance): N=50000, E=1600000, D=256, H=8, C=32.
#define DD 256
#define HH 8
#define CC 32
#define MAXN 50176          // 392 * 128
#define MAXE 1600000
#define SCAN_BLK 1024
#define MAXSB 64
#define NB 512              // total output cols (Wlin | Wres)

// ---------------- scratch (device globals; no allocation allowed) ----------
__device__ float g_x[MAXN * DD];             // x fp32 (alpha pass)
__device__ __half g_xh[MAXN * DD];           // x fp16 (message gather)
__device__ float g_al[MAXN * HH];
__device__ float g_ar[MAXN * HH];
__device__ int   g_cnt[MAXN + 1];
__device__ int   g_off[MAXN + 1];
__device__ int   g_cur[MAXN];
__device__ int2  g_edge[MAXE];               // dst-sorted payload: (src, w bits)
__device__ int   g_bsum[MAXSB];
__device__ int   g_bpre[MAXSB];
// bf16 hi/lo splits for tensor-core GEMM
__device__ __nv_bfloat16 g_ahi[MAXN * DD];
__device__ __nv_bfloat16 g_alo[MAXN * DD];
__device__ __nv_bfloat16 g_bhi[NB * DD];     // [n][k], k contiguous (W transposed)
__device__ __nv_bfloat16 g_blo[NB * DD];

// ---------------- helpers (baseline PTX, sm_80+) ---------------------------
__device__ __forceinline__ uint32_t s2u(const void* p) {
    uint32_t a;
    asm("{ .reg .u64 t; cvta.to.shared.u64 t, %1; cvt.u32.u64 %0, t; }"
        : "=r"(a) : "l"(p));
    return a;
}
__device__ __forceinline__ void ldsm4(uint32_t* r, uint32_t addr) {
    asm volatile("ldmatrix.sync.aligned.m8n8.x4.shared.b16 {%0,%1,%2,%3}, [%4];"
                 : "=r"(r[0]), "=r"(r[1]), "=r"(r[2]), "=r"(r[3]) : "r"(addr));
}
__device__ __forceinline__ void mma16816(float* d, const uint32_t* a,
                                         const uint32_t* b) {
    asm volatile(
        "mma.sync.aligned.m16n8k16.row.col.f32.bf16.bf16.f32 "
        "{%0,%1,%2,%3}, {%4,%5,%6,%7}, {%8,%9}, {%0,%1,%2,%3};"
        : "+f"(d[0]), "+f"(d[1]), "+f"(d[2]), "+f"(d[3])
        : "r"(a[0]), "r"(a[1]), "r"(a[2]), "r"(a[3]), "r"(b[0]), "r"(b[1]));
}
__device__ __forceinline__ void cpasync16(uint32_t dst, const void* src) {
    asm volatile("cp.async.ca.shared.global [%0], [%1], 16;"
                 :: "r"(dst), "l"(src));
}

// ---------------- K-1a: split feat into bf16 hi/lo -------------------------
__global__ void conv_feat(const float* __restrict__ feat, int N)
{
    int i = blockIdx.x * blockDim.x + threadIdx.x;       // float4 index
    if (i >= N * (DD / 4)) return;
    float4 v = ((const float4*)feat)[i];
    __nv_bfloat16 h0 = __float2bfloat16(v.x);
    __nv_bfloat16 h1 = __float2bfloat16(v.y);
    __nv_bfloat16 h2 = __float2bfloat16(v.z);
    __nv_bfloat16 h3 = __float2bfloat16(v.w);
    __nv_bfloat16 l0 = __float2bfloat16(v.x - __bfloat162float(h0));
    __nv_bfloat16 l1 = __float2bfloat16(v.y - __bfloat162float(h1));
    __nv_bfloat16 l2 = __float2bfloat16(v.z - __bfloat162float(h2));
    __nv_bfloat16 l3 = __float2bfloat16(v.w - __bfloat162float(h3));
    ((__nv_bfloat162*)g_ahi)[i * 2]     = __nv_bfloat162(h0, h1);
    ((__nv_bfloat162*)g_ahi)[i * 2 + 1] = __nv_bfloat162(h2, h3);
    ((__nv_bfloat162*)g_alo)[i * 2]     = __nv_bfloat162(l0, l1);
    ((__nv_bfloat162*)g_alo)[i * 2 + 1] = __nv_bfloat162(l2, l3);
}

// ---------------- K-1b: transpose+split W into B [n][k] bf16 hi/lo ---------
__global__ void conv_w(const float* __restrict__ Wlin, const float* __restrict__ Wres)
{
    int idx = blockIdx.x * blockDim.x + threadIdx.x;     // n*256 + k
    if (idx >= NB * DD) return;
    int n = idx >> 8, k = idx & 255;
    float v = (n < 256) ? Wlin[k * 256 + n] : Wres[k * 256 + (n - 256)];
    __nv_bfloat16 h = __float2bfloat16(v);
    __nv_bfloat16 l = __float2bfloat16(v - __bfloat162float(h));
    g_bhi[idx] = h;
    g_blo[idx] = l;
}

// ---------------- K0: HMMA dual GEMM, cp.async double-buffered -------------
// CTA: 128x128 output, 256 thr (8 warps, 4m x 2n), BK=32, smem rows 80B pad.
#define LDS 80                     // bytes per smem row — conflict-free ldmatrix
#define TILEB (128 * LDS)          // 10240 B per tile
#define SMEM_GEMM (2 * 4 * TILEB)  // 81920 B (double buffer x 4 tiles)
extern __shared__ char smg[];
__global__ __launch_bounds__(256) void gemm_tc(float* __restrict__ Res, int M)
{
    uint32_t sb = s2u(smg);
    int tid = threadIdx.x;
    int wid = tid >> 5, lane = tid & 31;
    int wm = wid >> 1;          // 0..3 -> m offset wm*32
    int wn = wid & 1;           // 0..1 -> n offset wn*64
    int bm = blockIdx.x, bn = blockIdx.y;

    // per-lane ldmatrix offsets
    uint32_t offA = (uint32_t)((lane & 15) * LDS + (lane >> 4) * 16);
    uint32_t offB = (uint32_t)(((lane & 7) + ((lane >> 4) & 1) * 8) * LDS +
                               ((lane >> 3) & 1) * 16);

    const __nv_bfloat16* srcs[4] = {
        g_ahi + (size_t)bm * 128 * DD, g_alo + (size_t)bm * 128 * DD,
        g_bhi + (size_t)bn * 128 * DD, g_blo + (size_t)bn * 128 * DD};

    // per-thread load coords (2 x 16B per tile)
    int r0 = (tid * 2) >> 2, s0 = (tid * 2) & 3;
    int r1 = (tid * 2 + 1) >> 2, s1 = (tid * 2 + 1) & 3;

    float acc[2][8][4];
    #pragma unroll
    for (int mt = 0; mt < 2; mt++)
        #pragma unroll
        for (int nt = 0; nt < 8; nt++)
            #pragma unroll
            for (int j = 0; j < 4; j++) acc[mt][nt][j] = 0.f;

    // issue loads for chunk kc into buffer b
    auto issue = [&](int kc, int b) {
        uint32_t bufb = sb + (uint32_t)b * 4 * TILEB;
        #pragma unroll
        for (int m = 0; m < 4; m++) {
            const __nv_bfloat16* P = srcs[m] + kc * 32;
            cpasync16(bufb + m * TILEB + r0 * LDS + s0 * 16,
                      P + (size_t)r0 * DD + s0 * 8);
            cpasync16(bufb + m * TILEB + r1 * LDS + s1 * 16,
                      P + (size_t)r1 * DD + s1 * 8);
        }
        asm volatile("cp.async.commit_group;" ::: "memory");
    };

    issue(0, 0);
    for (int kc = 0; kc < 8; kc++) {
        if (kc < 7) {
            issue(kc + 1, (kc + 1) & 1);
            asm volatile("cp.async.wait_group 1;" ::: "memory");
        } else {
            asm volatile("cp.async.wait_group 0;" ::: "memory");
        }
        __syncthreads();

        uint32_t bufb = sb + (uint32_t)(kc & 1) * 4 * TILEB;
        uint32_t aHi = bufb, aLo = bufb + TILEB;
        uint32_t bHi = bufb + 2 * TILEB, bLo = bufb + 3 * TILEB;

        #pragma unroll
        for (int ks = 0; ks < 2; ks++) {        // two k=16 steps
            uint32_t kb = ks * 32;
            uint32_t ah[2][4], al[2][4];
            #pragma unroll
            for (int mt = 0; mt < 2; mt++) {
                uint32_t ro = (uint32_t)((wm * 32 + mt * 16) * LDS) + offA + kb;
                ldsm4(ah[mt], aHi + ro);
                ldsm4(al[mt], aLo + ro);
            }
            uint32_t bh[4][4], bl[4][4];
            #pragma unroll
            for (int np = 0; np < 4; np++) {
                uint32_t ro = (uint32_t)((wn * 64 + np * 16) * LDS) + offB + kb;
                ldsm4(bh[np], bHi + ro);
                ldsm4(bl[np], bLo + ro);
            }
            #pragma unroll
            for (int mt = 0; mt < 2; mt++)
                #pragma unroll
                for (int nt = 0; nt < 8; nt++) {
                    float* d = acc[mt][nt];
                    const uint32_t* Bh2 = &bh[nt >> 1][(nt & 1) * 2];
                    const uint32_t* Bl2 = &bl[nt >> 1][(nt & 1) * 2];
                    mma16816(d, ah[mt], Bh2);   // hi*hi
                    mma16816(d, ah[mt], Bl2);   // hi*lo
                    mma16816(d, al[mt], Bh2);   // lo*hi
                }
        }
        __syncthreads();
    }

    // epilogue: fp32 to g_x (bn 0,1) or Res (bn 2,3); fp16 shadow for gather
    #pragma unroll
    for (int mt = 0; mt < 2; mt++) {
        int row0 = bm * 128 + wm * 32 + mt * 16 + (lane >> 2);
        #pragma unroll
        for (int half = 0; half < 2; half++) {
            int row = row0 + half * 8;
            if (row < M) {
                int col0 = wn * 64 + (lane & 3) * 2;
                if (bn < 2) {
                    float* base = g_x + (size_t)row * DD + bn * 128;
                    __half* hb = g_xh + (size_t)row * DD + bn * 128;
                    #pragma unroll
                    for (int nt = 0; nt < 8; nt++) {
                        float a0 = acc[mt][nt][half * 2];
                        float a1 = acc[mt][nt][half * 2 + 1];
                        *(float2*)(base + col0 + nt * 8) = make_float2(a0, a1);
                        *(__half2*)(hb + col0 + nt * 8) = __floats2half2_rn(a0, a1);
                    }
                } else {
                    float* base = Res + (size_t)row * DD + (bn - 2) * 128;
                    #pragma unroll
                    for (int nt = 0; nt < 8; nt++) {
                        float2 v = make_float2(acc[mt][nt][half * 2],
                                               acc[mt][nt][half * 2 + 1]);
                        *(float2*)(base + col0 + nt * 8) = v;
                    }
                }
            }
        }
    }
}

// ---------------- K1: warp-per-node alpha_l/alpha_r ------------------------
__global__ __launch_bounds__(256) void alpha_k(
    const float* __restrict__ attl, const float* __restrict__ attr, int N)
{
    __shared__ float sl[DD], sr[DD];
    if (threadIdx.x < DD) {
        sl[threadIdx.x] = attl[threadIdx.x];
        sr[threadIdx.x] = attr[threadIdx.x];
    }
    __syncthreads();
    int gtid = blockIdx.x * blockDim.x + threadIdx.x;
    int node = gtid >> 5;
    int lane = threadIdx.x & 31;
    if (node >= N) return;

    const float4* xr = (const float4*)(g_x + (size_t)node * DD + lane * 8);
    float4 v0 = xr[0], v1 = xr[1];
    const float* al = sl + lane * 8;
    const float* ar = sr + lane * 8;
    float sa = v0.x * al[0] + v0.y * al[1] + v0.z * al[2] + v0.w * al[3]
             + v1.x * al[4] + v1.y * al[5] + v1.z * al[6] + v1.w * al[7];
    float sb = v0.x * ar[0] + v0.y * ar[1] + v0.z * ar[2] + v0.w * ar[3]
             + v1.x * ar[4] + v1.y * ar[5] + v1.z * ar[6] + v1.w * ar[7];
    sa += __shfl_xor_sync(0xffffffffu, sa, 1);
    sa += __shfl_xor_sync(0xffffffffu, sa, 2);
    sb += __shfl_xor_sync(0xffffffffu, sb, 1);
    sb += __shfl_xor_sync(0xffffffffu, sb, 2);
    if ((lane & 3) == 0) {
        int h = lane >> 2;
        g_al[node * HH + h] = sa;
        g_ar[node * HH + h] = sb;
    }
}

// ---------------- K2a: zero histogram (head of edge stream) ----------------
__global__ void zero_cnt(int N)
{
    int i = blockIdx.x * blockDim.x + threadIdx.x;
    if (i <= N) g_cnt[i] = 0;
}

// ---------------- K2b: histogram of destination degrees --------------------
__global__ void hist_dst(const int* __restrict__ ei, int E)
{
    int e = blockIdx.x * blockDim.x + threadIdx.x;
    if (e >= E) return;
    atomicAdd(&g_cnt[ei[E + e]], 1);
}

// ---------------- K3a/b/c: 3-phase exclusive scan --------------------------
__global__ void scan_phase1(int N)
{
    __shared__ int wsum[8];
    int t = threadIdx.x;
    int base = blockIdx.x * SCAN_BLK + t * 4;
    int s = 0;
    #pragma unroll
    for (int j = 0; j < 4; j++) s += (base + j < N) ? g_cnt[base + j] : 0;
    #pragma unroll
    for (int off = 16; off; off >>= 1) s += __shfl_xor_sync(0xffffffffu, s, off);
    if ((t & 31) == 0) wsum[t >> 5] = s;
    __syncthreads();
    if (t == 0) {
        int tot = 0;
        #pragma unroll
        for (int i = 0; i < 8; i++) tot += wsum[i];
        g_bsum[blockIdx.x] = tot;
    }
}
__global__ void scan_phase2(int nb)
{
    __shared__ int wt[2];
    int t = threadIdx.x;
    int lane = t & 31, wid = t >> 5;
    int mine = (t < nb) ? g_bsum[t] : 0;
    int v = mine;
    #pragma unroll
    for (int off = 1; off < 32; off <<= 1) {
        int u = __shfl_up_sync(0xffffffffu, v, off);
        if (lane >= off) v += u;
    }
    if (lane == 31) wt[wid] = v;
    __syncthreads();
    if (wid == 1) v += wt[0];
    if (t < nb) g_bpre[t] = v - mine;
}
__global__ void scan_phase3(int N, int E)
{
    __shared__ int warp_tot[8];
    int t = threadIdx.x;
    int lane = t & 31, wid = t >> 5;
    int base = blockIdx.x * SCAN_BLK + t * 4;
    int c[4];
    #pragma unroll
    for (int j = 0; j < 4; j++) c[j] = (base + j < N) ? g_cnt[base + j] : 0;
    int tsum = c[0] + c[1] + c[2] + c[3];
    int v = tsum;
    #pragma unroll
    for (int off = 1; off < 32; off <<= 1) {
        int u = __shfl_up_sync(0xffffffffu, v, off);
        if (lane >= off) v += u;
    }
    if (lane == 31) warp_tot[wid] = v;
    __syncthreads();
    if (wid == 0) {
        int wv = (lane < 8) ? warp_tot[lane] : 0;
        #pragma unroll
        for (int off = 1; off < 8; off <<= 1) {
            int u = __shfl_up_sync(0xffffffffu, wv, off);
            if (lane >= off) wv += u;
        }
        if (lane < 8) warp_tot[lane] = wv;
    }
    __syncthreads();
    int excl = v - tsum + ((wid > 0) ? warp_tot[wid - 1] : 0) + g_bpre[blockIdx.x];
    #pragma unroll
    for (int j = 0; j < 4; j++) {
        int idx = base + j;
        if (idx < N) { g_off[idx] = excl; g_cur[idx] = excl; }
        excl += c[j];
    }
    if (blockIdx.x == 0 && t == 0) g_off[N] = E;
}

// ---------------- K4: payload scatter (counting-sort by dst) ---------------
__global__ void scatter_sort(const int* __restrict__ ei,
                             const float* __restrict__ ew, int E)
{
    int e = blockIdx.x * blockDim.x + threadIdx.x;
    if (e >= E) return;
    int dst = ei[E + e];
    int pos = atomicAdd(&g_cur[dst], 1);
    g_edge[pos] = make_int2(ei[e], __float_as_int(ew[e]));
}

// ---------------- K5: fused gather (fp16 msgs) + softmax + elu + residual --
__global__ __launch_bounds__(256) void gather_fused(float* __restrict__ out, int N)
{
    int node = (blockIdx.x * blockDim.x + threadIdx.x) >> 5;
    int lane = threadIdx.x & 31;
    if (node >= N) return;

    int beg = g_off[node];
    int end = g_off[node + 1];
    int hl = lane & 7;
    float ar = g_ar[node * HH + hl];

    float den = 0.f;
    float acc[8];
    #pragma unroll
    for (int k = 0; k < 8; k++) acc[k] = 0.f;

    #pragma unroll 2
    for (int i = beg; i < end; i++) {
        int2 p = g_edge[i];
        int src = p.x;
        float w = __int_as_float(p.y);
        float a = w * (g_al[src * HH + hl] + ar);
        a = fmaxf(a, 0.2f * a);                 // leaky_relu(0.2)
        float ex = __expf(a);
        den += ex;
        float coeff = __shfl_sync(0xffffffffu, ex, lane >> 2);
        uint4 q = *(const uint4*)(g_xh + (size_t)src * DD + lane * 8);
        const __half2* hp = (const __half2*)&q;
        float2 f0 = __half22float2(hp[0]);
        float2 f1 = __half22float2(hp[1]);
        float2 f2 = __half22float2(hp[2]);
        float2 f3 = __half22float2(hp[3]);
        acc[0] = fmaf(coeff, f0.x, acc[0]);
        acc[1] = fmaf(coeff, f0.y, acc[1]);
        acc[2] = fmaf(coeff, f1.x, acc[2]);
        acc[3] = fmaf(coeff, f1.y, acc[3]);
        acc[4] = fmaf(coeff, f2.x, acc[4]);
        acc[5] = fmaf(coeff, f2.y, acc[5]);
        acc[6] = fmaf(coeff, f3.x, acc[6]);
        acc[7] = fmaf(coeff, f3.y, acc[7]);
    }

    float d = __shfl_sync(0xffffffffu, den, lane >> 2) + 1e-16f;
    float inv = 1.0f / d;

    float* o = out + (size_t)node * DD + lane * 8;   // holds residual
    float4 r0 = *(float4*)o;
    float4 r1 = *(float4*)(o + 4);
    float v;
    v = acc[0] * inv; r0.x += (v > 0.f ? v : expm1f(v));
    v = acc[1] * inv; r0.y += (v > 0.f ? v : expm1f(v));
    v = acc[2] * inv; r0.z += (v > 0.f ? v : expm1f(v));
    v = acc[3] * inv; r0.w += (v > 0.f ? v : expm1f(v));
    v = acc[4] * inv; r1.x += (v > 0.f ? v : expm1f(v));
    v = acc[5] * inv; r1.y += (v > 0.f ? v : expm1f(v));
    v = acc[6] * inv; r1.z += (v > 0.f ? v : expm1f(v));
    v = acc[7] * inv; r1.w += (v > 0.f ? v : expm1f(v));
    *(float4*)o       = r0;
    *(float4*)(o + 4) = r1;
}

// ---------------------------------------------------------------------------
extern "C" void kernel_launch(void* const* d_in, const int* in_sizes, int n_in,
                              void* d_out, int out_size)
{
    const float* feat = (const float*)d_in[0];
    const float* ew   = (const float*)d_in[1];
    const float* Wlin = (const float*)d_in[2];
    const float* attl = (const float*)d_in[3];
    const float* attr = (const float*)d_in[4];
    const float* Wres = (const float*)d_in[5];
    const int*   ei   = (const int*)d_in[6];
    float* out = (float*)d_out;

    int HC = in_sizes[3];            // 256
    int D  = in_sizes[2] / HC;       // 256
    int N  = in_sizes[0] / D;        // 50000
    int E  = in_sizes[1];            // 1600000

    static cudaStream_t s2 = nullptr;
    static cudaEvent_t evFork = nullptr, evJoin = nullptr;
    if (!s2) {
        cudaStreamCreateWithFlags(&s2, cudaStreamNonBlocking);
        cudaEventCreateWithFlags(&evFork, cudaEventDisableTiming);
        cudaEventCreateWithFlags(&evJoin, cudaEventDisableTiming);
        cudaFuncSetAttribute(gemm_tc,
                             cudaFuncAttributeMaxDynamicSharedMemorySize,
                             SMEM_GEMM);
    }

    // fork: edge chain on s2
    cudaEventRecord(evFork, 0);
    cudaStreamWaitEvent(s2, evFork, 0);

    zero_cnt<<<(N + 256) / 256, 256, 0, s2>>>(N);
    hist_dst<<<(E + 255) / 256, 256, 0, s2>>>(ei, E);
    int nb = (N + SCAN_BLK - 1) / SCAN_BLK;
    scan_phase1<<<nb, 256, 0, s2>>>(N);
    scan_phase2<<<1, 64, 0, s2>>>(nb);
    scan_phase3<<<nb, 256, 0, s2>>>(N, E);
    scatter_sort<<<(E + 255) / 256, 256, 0, s2>>>(ei, ew, E);
    cudaEventRecord(evJoin, s2);

    // main chain on default stream
    conv_feat<<<(N * (DD / 4) + 255) / 256, 256>>>(feat, N);
    conv_w<<<(NB * DD + 255) / 256, 256>>>(Wlin, Wres);

    dim3 gGemm((N + 127) / 128, 4);
    gemm_tc<<<gGemm, 256, SMEM_GEMM>>>(out, N);

    alpha_k<<<(N * 32 + 255) / 256, 256>>>(attl, attr, N);

    // join: gather needs both chains
    cudaStreamWaitEvent(0, evJoin, 0);
    gather_fused<<<(N * 32 + 255) / 256, 256>>>(out, N);
}